// round 6
// baseline (speedup 1.0000x reference)
#include <cuda_runtime.h>
#include <cuda_fp16.h>
#include <mma.h>
#include <cstdint>
#include <math.h>

using namespace nvcuda;

#define BB 4
#define SS 2048
#define EE 1024
#define HH 16
#define DD 64
#define MM (BB*SS)   // 8192

// ---- tiled global layouts (contiguous tiles for cp.async.bulk) ----
#define AT_LD 40
#define AT_E  (128*AT_LD)           // 5120 halves per A/W tile (128 rows x 40)
#define AT_B  (AT_E*2)              // 10240 bytes
#define WSLOT ((size_t)8*32*AT_E)   // one weight slot: 8 nb x 32 kc tiles
#define KT_LD 72
#define KT_E  (64*KT_LD)            // 4608 halves per QKV tile (64 rows x 72)
#define KT_B  (KT_E*2)              // 9216 bytes

// ---------------- device scratch (allocation-free contract) ----------------
__device__ __align__(16) __half g_xh[(size_t)64*32*AT_E];      // A tiles [mb][kc][128x40]
__device__ __align__(16) __half g_wth[4*WSLOT];                // W^T hi tiles [slot][nb][kc]
__device__ __align__(16) __half g_wtl[4*WSLOT];                // W^T lo tiles
__device__ __align__(16) __half g_qh[(size_t)64*32*KT_E];      // Q tiles [bh][qt][64x72] (pre-scaled 1/8)
__device__ __align__(16) __half g_kh[(size_t)64*32*KT_E];
__device__ __align__(16) __half g_kl[(size_t)64*32*KT_E];
__device__ __align__(16) __half g_vh[(size_t)64*32*KT_E];
__device__ __align__(16) __half g_vl[(size_t)64*32*KT_E];

// ---------------- helpers ----------------
__device__ __forceinline__ uint32_t smem_u32(const void* p) {
    uint32_t a;
    asm("{ .reg .u64 t; cvta.to.shared.u64 t, %1; cvt.u32.u64 %0, t; }" : "=r"(a) : "l"(p));
    return a;
}
#define CP_ASYNC16(sa, g)  asm volatile("cp.async.cg.shared.global [%0], [%1], 16;" :: "r"(sa), "l"(g) : "memory")
#define CP_ASYNC_COMMIT()  asm volatile("cp.async.commit_group;" ::: "memory")
#define CP_ASYNC_WAIT0()   asm volatile("cp.async.wait_group 0;" ::: "memory")
#define MBARRIER_INIT(a, c) asm volatile("mbarrier.init.shared.b64 [%0], %1;" :: "r"(a), "r"(c) : "memory")
#define MBAR_EXPECT_TX(mb, n) asm volatile("mbarrier.arrive.expect_tx.shared.b64 _, [%0], %1;" :: "r"(mb), "r"(n) : "memory")
#define BULK_G2S(sa, g, bytes, mb) \
    asm volatile("cp.async.bulk.shared::cluster.global.mbarrier::complete_tx::bytes [%0], [%1], %2, [%3];" \
        :: "r"(sa), "l"(g), "r"(bytes), "r"(mb) : "memory")
#define MBARRIER_WAIT_PARITY(a, ph) do { \
    uint32_t _m = (a), _p = (ph), _d; \
    asm volatile("{\n\t.reg .pred p;\n\tmbarrier.try_wait.parity.acquire.cta.shared::cta.b64 p, [%1], %2;\n\tselp.b32 %0, 1, 0, p;\n\t}" \
        : "=r"(_d) : "r"(_m), "r"(_p) : "memory"); \
    if (!_d) { \
        asm volatile("{\n\t.reg .pred P1;\n\tWL_%=:\n\tmbarrier.try_wait.parity.acquire.cta.shared::cta.b64 P1, [%0], %1, 0x989680;\n\t@P1 bra.uni WD_%=;\n\tbra.uni WL_%=;\n\tWD_%=:\n\t}" \
            :: "r"(_m), "r"(_p) : "memory"); \
    } } while (0)

__device__ __forceinline__ void split2h(float v, __half& h, __half& l) {
    h = __float2half_rn(v);
    l = __float2half_rn(v - __half2float(h));
}

// ---------------- converters ----------------
// x [8192,1024] fp32 -> fp16 A tiles
__global__ __launch_bounds__(256) void conv_x(const float* __restrict__ in) {
    size_t i = ((size_t)blockIdx.x * 256 + threadIdx.x) * 8;
    const int m = (int)(i >> 10), k = (int)(i & 1023);
    float4 a = *(const float4*)(in + i);
    float4 b = *(const float4*)(in + i + 4);
    __half2 o[4];
    o[0] = __floats2half2_rn(a.x, a.y);
    o[1] = __floats2half2_rn(a.z, a.w);
    o[2] = __floats2half2_rn(b.x, b.y);
    o[3] = __floats2half2_rn(b.z, b.w);
    size_t dst = ((size_t)((m >> 7) * 32 + (k >> 5))) * AT_E + (m & 127) * AT_LD + (k & 31);
    *(uint4*)(g_xh + dst) = *(uint4*)o;
}

// W [K,N] fp32 -> W^T hi/lo tiles at slot widx
__global__ __launch_bounds__(256) void conv_w(const float* __restrict__ W, int widx) {
    __shared__ float t[32][33];
    const int tx = threadIdx.x & 31, ty = threadIdx.x >> 5;
    const int n0 = blockIdx.x * 32, k0 = blockIdx.y * 32;
    __half* wh = g_wth + (size_t)widx * WSLOT;
    __half* wl = g_wtl + (size_t)widx * WSLOT;
    #pragma unroll
    for (int j = 0; j < 4; j++)
        t[ty + 8*j][tx] = W[(size_t)(k0 + ty + 8*j) * 1024 + n0 + tx];
    __syncthreads();
    #pragma unroll
    for (int j = 0; j < 4; j++) {
        float v = t[tx][ty + 8*j];
        __half hh, ll; split2h(v, hh, ll);
        const int n = n0 + ty + 8*j, k = k0 + tx;
        size_t o = ((size_t)((n >> 7) * 32 + (k >> 5))) * AT_E + (n & 127) * AT_LD + (k & 31);
        wh[o] = hh;
        wl[o] = ll;
    }
}

// ---------------- WMMA fp16x2 GEMM, bulk-copy fed ----------------
#define STAGE_E (3 * AT_E)
#define STAGE_B (3 * AT_B)           // 30720
#define GEMM_SMEM 65536              // max(2*STAGE_B=61440, epilogue 8*64*32*4)

template<int MODE>
__global__ __launch_bounds__(256)
void wgemm(const float* __restrict__ bias, float* __restrict__ outp, int widx)
{
    extern __shared__ char smraw[];
    __half* s = (__half*)smraw;
    const uint32_t sbase = smem_u32(smraw);
    __shared__ __align__(8) unsigned long long s_mbar[2];

    const int tid  = threadIdx.x;
    const int wid  = tid >> 5, lane = tid & 31;
    const int wm   = wid >> 2, wn = wid & 3;
    const int m0   = blockIdx.y * 128;
    const int n0   = blockIdx.x * 128;

    const uint32_t mb0 = smem_u32(&s_mbar[0]);
    const uint32_t mb1 = smem_u32(&s_mbar[1]);
    if (tid == 0) { MBARRIER_INIT(mb0, 1); MBARRIER_INIT(mb1, 1); }
    __syncthreads();

    const __half* Asrc = g_xh + (size_t)blockIdx.y * 32 * AT_E;
    const __half* Bhs  = g_wth + (size_t)widx * WSLOT + (size_t)blockIdx.x * 32 * AT_E;
    const __half* Bls  = g_wtl + (size_t)widx * WSLOT + (size_t)blockIdx.x * 32 * AT_E;

    wmma::fragment<wmma::accumulator, 16, 16, 16, float> acc[4][2];
    #pragma unroll
    for (int i = 0; i < 4; i++)
        #pragma unroll
        for (int j = 0; j < 2; j++) wmma::fill_fragment(acc[i][j], 0.0f);

    if (tid == 0) {
        MBAR_EXPECT_TX(mb0, STAGE_B);
        BULK_G2S(sbase,            Asrc, AT_B, mb0);
        BULK_G2S(sbase + AT_B,     Bhs,  AT_B, mb0);
        BULK_G2S(sbase + 2*AT_B,   Bls,  AT_B, mb0);
    }

    for (int ch = 0; ch < 32; ch++) {
        if (tid == 0 && ch < 31) {
            const int nx = ch + 1;
            const uint32_t m = (nx & 1) ? mb1 : mb0;
            const uint32_t sb = sbase + (nx & 1) * STAGE_B;
            MBAR_EXPECT_TX(m, STAGE_B);
            BULK_G2S(sb,            Asrc + (size_t)nx * AT_E, AT_B, m);
            BULK_G2S(sb + AT_B,     Bhs  + (size_t)nx * AT_E, AT_B, m);
            BULK_G2S(sb + 2*AT_B,   Bls  + (size_t)nx * AT_E, AT_B, m);
        }
        MBARRIER_WAIT_PARITY((ch & 1) ? mb1 : mb0, (ch >> 1) & 1);

        const __half* st  = s + (ch & 1) * STAGE_E;
        const __half* sa  = st;
        const __half* sbh = st + AT_E;
        const __half* sbl = st + 2 * AT_E;

        #pragma unroll
        for (int ks = 0; ks < 2; ks++) {
            wmma::fragment<wmma::matrix_a, 16, 16, 16, __half, wmma::row_major> a[4];
            #pragma unroll
            for (int i = 0; i < 4; i++)
                wmma::load_matrix_sync(a[i], sa + (size_t)(wm * 64 + i * 16) * AT_LD + ks * 16, AT_LD);
            #pragma unroll
            for (int j = 0; j < 2; j++) {
                wmma::fragment<wmma::matrix_b, 16, 16, 16, __half, wmma::col_major> bh, bl;
                wmma::load_matrix_sync(bh, sbh + (size_t)(wn * 32 + j * 16) * AT_LD + ks * 16, AT_LD);
                wmma::load_matrix_sync(bl, sbl + (size_t)(wn * 32 + j * 16) * AT_LD + ks * 16, AT_LD);
                #pragma unroll
                for (int i = 0; i < 4; i++) wmma::mma_sync(acc[i][j], a[i], bh, acc[i][j]);
                #pragma unroll
                for (int i = 0; i < 4; i++) wmma::mma_sync(acc[i][j], a[i], bl, acc[i][j]);
            }
        }
        __syncthreads();
    }

    // epilogue
    float* stg = (float*)smraw + (size_t)wid * (64 * 32);
    #pragma unroll
    for (int i = 0; i < 4; i++)
        #pragma unroll
        for (int j = 0; j < 2; j++)
            wmma::store_matrix_sync(stg + i * 16 * 32 + j * 16, acc[i][j], 32, wmma::mem_row_major);
    __syncwarp();

    const int nw0 = n0 + wn * 32;
    #pragma unroll
    for (int l = 0; l < 16; l++) {
        int idx = lane + l * 32;
        int r   = idx >> 3;
        int c4  = (idx & 7) * 4;
        float4 v = *(const float4*)(stg + r * 32 + c4);
        float4 bv = *(const float4*)&bias[nw0 + c4];
        v.x += bv.x; v.y += bv.y; v.z += bv.z; v.w += bv.w;
        const int m = m0 + wm * 64 + r;
        if (MODE < 3) {
            const int b = m >> 11, sq = m & 2047;
            const int hd = nw0 >> 6, d0 = (nw0 & 63) + c4;
            const int bh = b * HH + hd;
            const size_t o = ((size_t)(bh * 32 + (sq >> 6))) * KT_E + (sq & 63) * KT_LD + d0;
            if (MODE == 0) {
                *(__half2*)(g_qh + o)     = __floats2half2_rn(v.x * 0.125f, v.y * 0.125f);
                *(__half2*)(g_qh + o + 2) = __floats2half2_rn(v.z * 0.125f, v.w * 0.125f);
            } else {
                __half* dh = (MODE == 1) ? g_kh : g_vh;
                __half* dl = (MODE == 1) ? g_kl : g_vl;
                __half h0,h1,h2,h3,l0,l1,l2,l3;
                split2h(v.x,h0,l0); split2h(v.y,h1,l1); split2h(v.z,h2,l2); split2h(v.w,h3,l3);
                *(__half2*)(dh + o)     = __halves2half2(h0, h1);
                *(__half2*)(dh + o + 2) = __halves2half2(h2, h3);
                *(__half2*)(dl + o)     = __halves2half2(l0, l1);
                *(__half2*)(dl + o + 2) = __halves2half2(l2, l3);
            }
        } else {
            *(float4*)&outp[(size_t)m * 1024 + nw0 + c4] = v;
        }
    }
}

// ---------------- WMMA fp16 flash attention, bulk-copy fed ----------------
#define F_LD  68
#define ATTN_SMEM (6 * KT_E * 2 + 2 * 64 * F_LD * 4)   // 90112

__global__ __launch_bounds__(128)
void attn3()
{
    extern __shared__ char smraw[];
    __half* sQ  = (__half*)smraw;
    __half* sKh = sQ  + KT_E;
    __half* sKl = sKh + KT_E;
    __half* sVh = sKl + KT_E;
    __half* sVl = sVh + KT_E;
    __half* sP  = sVl + KT_E;
    float* sS = (float*)(sP + KT_E);
    float* sO = sS + 64 * F_LD;
    __shared__ __align__(8) unsigned long long a_mbar;

    const int tid  = threadIdx.x;
    const int warp = tid >> 5;
    const int qt = blockIdx.x, hh = blockIdx.y, bb = blockIdx.z;
    const int row  = tid >> 1;
    const int half = tid & 1;
    const int bh = bb * HH + hh;

    const uint32_t amb = smem_u32(&a_mbar);
    const uint32_t uKh = smem_u32(sKh), uKl = smem_u32(sKl);
    const uint32_t uVh = smem_u32(sVh), uVl = smem_u32(sVl);

    if (tid == 0) MBARRIER_INIT(amb, 1);

    // load Q tile via cp.async (one time)
    const __half* qtile = g_qh + ((size_t)(bh * 32 + qt)) * KT_E;
    #pragma unroll
    for (int i = 0; i < 4; i++) {
        int u = i * 128 + tid;
        int r = u >> 3, sg = u & 7;
        CP_ASYNC16(smem_u32(sQ + r * KT_LD + sg * 8), qtile + r * KT_LD + sg * 8);
    }
    CP_ASYNC_COMMIT();

    for (int i = tid; i < 64 * F_LD; i += 128) sO[i] = 0.0f;

    CP_ASYNC_WAIT0();
    __syncthreads();

    wmma::fragment<wmma::matrix_a, 16, 16, 16, __half, wmma::row_major> aQ[4];
    #pragma unroll
    for (int kk = 0; kk < 4; kk++)
        wmma::load_matrix_sync(aQ[kk], sQ + (size_t)(warp * 16) * KT_LD + kk * 16, KT_LD);

    float m_i = -INFINITY, l_i = 0.0f;

    for (int kt = 0; kt <= qt; kt++) {
        __syncthreads();   // all done with previous K/V/P/sS
        if (tid == 0) {
            const size_t toff = ((size_t)(bh * 32 + kt)) * KT_E;
            MBAR_EXPECT_TX(amb, 4 * KT_B);
            BULK_G2S(uKh, g_kh + toff, KT_B, amb);
            BULK_G2S(uKl, g_kl + toff, KT_B, amb);
            BULK_G2S(uVh, g_vh + toff, KT_B, amb);
            BULK_G2S(uVl, g_vl + toff, KT_B, amb);
        }
        MBARRIER_WAIT_PARITY(amb, kt & 1);

        // ---- scores ----
        {
            wmma::fragment<wmma::accumulator, 16, 16, 16, float> accS[4];
            #pragma unroll
            for (int j = 0; j < 4; j++) wmma::fill_fragment(accS[j], 0.0f);
            #pragma unroll
            for (int kk = 0; kk < 4; kk++) {
                #pragma unroll
                for (int j = 0; j < 4; j++) {
                    wmma::fragment<wmma::matrix_b, 16, 16, 16, __half, wmma::col_major> bhf, blf;
                    wmma::load_matrix_sync(bhf, sKh + (size_t)(j * 16) * KT_LD + kk * 16, KT_LD);
                    wmma::load_matrix_sync(blf, sKl + (size_t)(j * 16) * KT_LD + kk * 16, KT_LD);
                    wmma::mma_sync(accS[j], aQ[kk], bhf, accS[j]);
                    wmma::mma_sync(accS[j], aQ[kk], blf, accS[j]);
                }
            }
            #pragma unroll
            for (int j = 0; j < 4; j++)
                wmma::store_matrix_sync(sS + (size_t)(warp * 16) * F_LD + j * 16, accS[j], F_LD, wmma::mem_row_major);
        }
        __syncthreads();

        // ---- softmax (2 threads per row) ----
        {
            const float* srow = sS + (size_t)row * F_LD + half * 32;
            const bool diag = (kt == qt);
            float mx = -INFINITY;
            #pragma unroll
            for (int c8 = 0; c8 < 8; c8++) {
                float4 v = *(const float4*)(srow + 4 * c8);
                if (diag) {
                    int c0 = half * 32 + 4 * c8;
                    if (c0 + 0 > row) v.x = -INFINITY;
                    if (c0 + 1 > row) v.y = -INFINITY;
                    if (c0 + 2 > row) v.z = -INFINITY;
                    if (c0 + 3 > row) v.w = -INFINITY;
                }
                mx = fmaxf(mx, fmaxf(fmaxf(v.x, v.y), fmaxf(v.z, v.w)));
            }
            mx = fmaxf(mx, __shfl_xor_sync(0xffffffffu, mx, 1));
            const float m_new = fmaxf(m_i, mx);
            const float alpha = __expf(m_i - m_new);
            float ps = 0.0f;
            __half* ph = sP + (size_t)row * KT_LD + half * 32;
            #pragma unroll
            for (int c8 = 0; c8 < 8; c8++) {
                float4 v = *(const float4*)(srow + 4 * c8);
                int c0 = half * 32 + 4 * c8;
                float p0 = (diag && c0 + 0 > row) ? 0.0f : __expf(v.x - m_new);
                float p1 = (diag && c0 + 1 > row) ? 0.0f : __expf(v.y - m_new);
                float p2 = (diag && c0 + 2 > row) ? 0.0f : __expf(v.z - m_new);
                float p3 = (diag && c0 + 3 > row) ? 0.0f : __expf(v.w - m_new);
                ps += p0 + p1 + p2 + p3;
                *(__half2*)(ph + 4*c8)     = __floats2half2_rn(p0, p1);
                *(__half2*)(ph + 4*c8 + 2) = __floats2half2_rn(p2, p3);
            }
            ps += __shfl_xor_sync(0xffffffffu, ps, 1);
            l_i = l_i * alpha + ps;
            m_i = m_new;
            float* orow = sO + (size_t)row * F_LD + half * 32;
            #pragma unroll
            for (int c8 = 0; c8 < 8; c8++) {
                float4 ov = *(const float4*)(orow + 4 * c8);
                ov.x *= alpha; ov.y *= alpha; ov.z *= alpha; ov.w *= alpha;
                *(float4*)(orow + 4 * c8) = ov;
            }
        }
        __syncthreads();

        // ---- PV ----
        {
            wmma::fragment<wmma::accumulator, 16, 16, 16, float> accO[4];
            #pragma unroll
            for (int j = 0; j < 4; j++) wmma::fill_fragment(accO[j], 0.0f);
            #pragma unroll
            for (int kk = 0; kk < 4; kk++) {
                wmma::fragment<wmma::matrix_a, 16, 16, 16, __half, wmma::row_major> aP;
                wmma::load_matrix_sync(aP, sP + (size_t)(warp * 16) * KT_LD + kk * 16, KT_LD);
                #pragma unroll
                for (int j = 0; j < 4; j++) {
                    wmma::fragment<wmma::matrix_b, 16, 16, 16, __half, wmma::row_major> bvh, bvl;
                    wmma::load_matrix_sync(bvh, sVh + (size_t)(kk * 16) * KT_LD + j * 16, KT_LD);
                    wmma::load_matrix_sync(bvl, sVl + (size_t)(kk * 16) * KT_LD + j * 16, KT_LD);
                    wmma::mma_sync(accO[j], aP, bvh, accO[j]);
                    wmma::mma_sync(accO[j], aP, bvl, accO[j]);
                }
            }
            #pragma unroll
            for (int j = 0; j < 4; j++)
                wmma::store_matrix_sync(sS + (size_t)(warp * 16) * F_LD + j * 16, accO[j], F_LD, wmma::mem_row_major);
        }
        __syncthreads();

        // ---- O += delta ----
        {
            const float* drow = sS + (size_t)row * F_LD + half * 32;
            float* orow = sO + (size_t)row * F_LD + half * 32;
            #pragma unroll
            for (int c8 = 0; c8 < 8; c8++) {
                float4 d = *(const float4*)(drow + 4 * c8);
                float4 o = *(const float4*)(orow + 4 * c8);
                o.x += d.x; o.y += d.y; o.z += d.z; o.w += d.w;
                *(float4*)(orow + 4 * c8) = o;
            }
        }
    }

    // epilogue: normalize + write fp16 A tiles (operand for O-projection)
    {
        const float inv = 1.0f / l_i;
        const float* orow = sO + (size_t)row * F_LD + half * 32;
        const int m = bb * SS + qt * 64 + row;
        const int kc = hh * 2 + half;
        const size_t go = ((size_t)((m >> 7) * 32 + kc)) * AT_E + (m & 127) * AT_LD;
        #pragma unroll
        for (int c8 = 0; c8 < 8; c8++) {
            float4 v = *(const float4*)(orow + 4 * c8);
            *(__half2*)(g_xh + go + 4*c8)     = __floats2half2_rn(v.x * inv, v.y * inv);
            *(__half2*)(g_xh + go + 4*c8 + 2) = __floats2half2_rn(v.z * inv, v.w * inv);
        }
    }
}

// ---------------------------------------------------------------------------
extern "C" void kernel_launch(void* const* d_in, const int* in_sizes, int n_in,
                              void* d_out, int out_size)
{
    const float* x  = (const float*)d_in[0];
    const float* Wq = (const float*)d_in[1];
    const float* bq = (const float*)d_in[2];
    const float* Wk = (const float*)d_in[3];
    const float* bk = (const float*)d_in[4];
    const float* Wv = (const float*)d_in[5];
    const float* bv = (const float*)d_in[6];
    const float* Wo = (const float*)d_in[7];
    const float* bo = (const float*)d_in[8];
    float* out = (float*)d_out;

    cudaFuncSetAttribute(wgemm<0>, cudaFuncAttributeMaxDynamicSharedMemorySize, GEMM_SMEM);
    cudaFuncSetAttribute(wgemm<1>, cudaFuncAttributeMaxDynamicSharedMemorySize, GEMM_SMEM);
    cudaFuncSetAttribute(wgemm<2>, cudaFuncAttributeMaxDynamicSharedMemorySize, GEMM_SMEM);
    cudaFuncSetAttribute(wgemm<3>, cudaFuncAttributeMaxDynamicSharedMemorySize, GEMM_SMEM);
    cudaFuncSetAttribute(attn3,    cudaFuncAttributeMaxDynamicSharedMemorySize, ATTN_SMEM);

    const dim3 gg(EE / 128, MM / 128);   // (8, 64)
    const dim3 wg(32, 32);

    // launches 5 and 6 are wgemm so ncu -s 5 -c 1 catches one regardless of off-by-one
    conv_x<<<MM * EE / 2048, 256>>>(x);
    conv_w<<<wg, 256>>>(Wq, 0);
    conv_w<<<wg, 256>>>(Wk, 1);
    conv_w<<<wg, 256>>>(Wv, 2);
    wgemm<0><<<gg, 256, GEMM_SMEM>>>(bq, nullptr, 0);
    wgemm<1><<<gg, 256, GEMM_SMEM>>>(bk, nullptr, 1);
    wgemm<2><<<gg, 256, GEMM_SMEM>>>(bv, nullptr, 2);
    conv_w<<<wg, 256>>>(Wo, 3);

    attn3<<<dim3(SS / 64, HH, BB), 128, ATTN_SMEM>>>();

    wgemm<3><<<gg, 256, GEMM_SMEM>>>(bo, out, 3);
}

// round 7
// speedup vs baseline: 1.3373x; 1.3373x over previous
#include <cuda_runtime.h>
#include <cuda_fp16.h>
#include <mma.h>
#include <cstdint>
#include <math.h>

using namespace nvcuda;

#define BB 4
#define SS 2048
#define EE 1024
#define HH 16
#define DD 64
#define MM (BB*SS)   // 8192

// ---------------- device scratch (allocation-free contract) ----------------
__device__ __align__(16) __half g_xh[(size_t)MM*EE];        // A operand fp16 [M,K]; attn writes O here
__device__ __align__(16) __half g_wth[4*(size_t)EE*EE];     // W^T hi [slot][N,K]
__device__ __align__(16) __half g_wtl[4*(size_t)EE*EE];     // W^T lo
__device__ __align__(16) __half g_qh[(size_t)BB*HH*SS*DD];  // Q fp16 (pre-scaled 1/8), [B,H,S,D]
__device__ __align__(16) __half g_kh[(size_t)BB*HH*SS*DD];  // K fp16
__device__ __align__(16) __half g_vh[(size_t)BB*HH*SS*DD];  // V fp16

// ---------------- helpers ----------------
__device__ __forceinline__ uint32_t smem_u32(const void* p) {
    uint32_t a;
    asm("{ .reg .u64 t; cvta.to.shared.u64 t, %1; cvt.u32.u64 %0, t; }" : "=r"(a) : "l"(p));
    return a;
}
#define CP_ASYNC16(sa, g)  asm volatile("cp.async.cg.shared.global [%0], [%1], 16;" :: "r"(sa), "l"(g) : "memory")
#define CP_ASYNC_COMMIT()  asm volatile("cp.async.commit_group;" ::: "memory")
#define CP_ASYNC_WAIT0()   asm volatile("cp.async.wait_group 0;" ::: "memory")
#define CP_ASYNC_WAIT1()   asm volatile("cp.async.wait_group 1;" ::: "memory")
#define CP_ASYNC_WAIT2()   asm volatile("cp.async.wait_group 2;" ::: "memory")

__device__ __forceinline__ void split2h(float v, __half& h, __half& l) {
    h = __float2half_rn(v);
    l = __float2half_rn(v - __half2float(h));
}

// ---------------- converters (R5 versions — fast) ----------------
__global__ __launch_bounds__(256) void conv_x(const float* __restrict__ in) {
    size_t i = ((size_t)blockIdx.x * 256 + threadIdx.x) * 8;
    float4 a = *(const float4*)(in + i);
    float4 b = *(const float4*)(in + i + 4);
    __half2 o[4];
    o[0] = __floats2half2_rn(a.x, a.y);
    o[1] = __floats2half2_rn(a.z, a.w);
    o[2] = __floats2half2_rn(b.x, b.y);
    o[3] = __floats2half2_rn(b.z, b.w);
    *(uint4*)(g_xh + i) = *(uint4*)o;
}

__global__ __launch_bounds__(256) void conv_w(const float* __restrict__ W, int widx) {
    __shared__ float t[32][33];
    const int tx = threadIdx.x & 31, ty = threadIdx.x >> 5;
    const int n0 = blockIdx.x * 32, k0 = blockIdx.y * 32;
    __half* wh = g_wth + (size_t)widx * EE * EE;
    __half* wl = g_wtl + (size_t)widx * EE * EE;
    #pragma unroll
    for (int j = 0; j < 4; j++)
        t[ty + 8*j][tx] = W[(size_t)(k0 + ty + 8*j) * 1024 + n0 + tx];
    __syncthreads();
    #pragma unroll
    for (int j = 0; j < 4; j++) {
        float v = t[tx][ty + 8*j];
        __half hh, ll; split2h(v, hh, ll);
        size_t o = (size_t)(n0 + ty + 8*j) * 1024 + k0 + tx;
        wh[o] = hh;
        wl[o] = ll;
    }
}

// ---------------- WMMA fp16x2 GEMM, 3-stage cp.async pipeline ----------------
#define PAD 40
#define TILE_B   (128 * PAD * 2)        // 10240 B
#define TILE_E   (128 * PAD)
#define STAGE_B  (3 * TILE_B)           // 30720: A, Bh, Bl
#define STAGE_E  (3 * TILE_E)
#define GEMM_SMEM (3 * STAGE_B)         // 92160 (also covers epilogue 65536)

__device__ __forceinline__ void stage_load(uint32_t sb,
    const __half* A, const __half* Bh, const __half* Bl, int k0, int tid)
{
    #pragma unroll
    for (int t = 0; t < 2; t++) {
        int u   = tid + t * 256;         // 0..511
        int row = u >> 2;
        int seg = u & 3;
        uint32_t off = (uint32_t)row * (PAD * 2) + seg * 16;
        size_t g = (size_t)row * 1024 + k0 + seg * 8;
        CP_ASYNC16(sb + off,              A  + g);
        CP_ASYNC16(sb + TILE_B + off,     Bh + g);
        CP_ASYNC16(sb + 2 * TILE_B + off, Bl + g);
    }
}

// MODE 0: fused QKV (blockIdx.z = 0/1/2 selects weight slot and q/k/v dst)
// MODE 1: O projection (slot 3, fp32 out)
template<int MODE>
__global__ __launch_bounds__(256)
void wgemm(const float* __restrict__ bias0, const float* __restrict__ bias1,
           const float* __restrict__ bias2, float* __restrict__ outp)
{
    extern __shared__ char smraw[];
    __half* s = (__half*)smraw;
    const uint32_t sbase = smem_u32(smraw);

    const int tid  = threadIdx.x;
    const int wid  = tid >> 5, lane = tid & 31;
    const int wm   = wid >> 2, wn = wid & 3;
    const int m0   = blockIdx.y * 128;
    const int n0   = blockIdx.x * 128;
    const int z    = (MODE == 0) ? blockIdx.z : 3;
    const float* bias = (MODE == 1) ? bias0 : (z == 0 ? bias0 : z == 1 ? bias1 : bias2);

    const __half* A  = g_xh + (size_t)m0 * 1024;
    const __half* Bh = g_wth + (size_t)z * EE * EE + (size_t)n0 * 1024;
    const __half* Bl = g_wtl + (size_t)z * EE * EE + (size_t)n0 * 1024;

    wmma::fragment<wmma::accumulator, 16, 16, 16, float> acc[4][2];
    #pragma unroll
    for (int i = 0; i < 4; i++)
        #pragma unroll
        for (int j = 0; j < 2; j++) wmma::fill_fragment(acc[i][j], 0.0f);

    stage_load(sbase,           A, Bh, Bl, 0,  tid); CP_ASYNC_COMMIT();
    stage_load(sbase + STAGE_B, A, Bh, Bl, 32, tid); CP_ASYNC_COMMIT();

    for (int kc = 0; kc < 32; kc++) {
        if (kc + 2 < 32) {
            stage_load(sbase + ((kc + 2) % 3) * STAGE_B, A, Bh, Bl, (kc + 2) * 32, tid);
            CP_ASYNC_COMMIT();
            CP_ASYNC_WAIT2();
        } else if (kc + 2 == 32) {
            CP_ASYNC_WAIT1();
        } else {
            CP_ASYNC_WAIT0();
        }
        __syncthreads();

        const __half* st  = s + (kc % 3) * STAGE_E;
        const __half* sa  = st;
        const __half* sbh = st + TILE_E;
        const __half* sbl = st + 2 * TILE_E;

        #pragma unroll
        for (int ks = 0; ks < 2; ks++) {
            wmma::fragment<wmma::matrix_a, 16, 16, 16, __half, wmma::row_major> a[4];
            #pragma unroll
            for (int i = 0; i < 4; i++)
                wmma::load_matrix_sync(a[i], sa + (size_t)(wm * 64 + i * 16) * PAD + ks * 16, PAD);
            #pragma unroll
            for (int j = 0; j < 2; j++) {
                wmma::fragment<wmma::matrix_b, 16, 16, 16, __half, wmma::col_major> bh, bl;
                wmma::load_matrix_sync(bh, sbh + (size_t)(wn * 32 + j * 16) * PAD + ks * 16, PAD);
                wmma::load_matrix_sync(bl, sbl + (size_t)(wn * 32 + j * 16) * PAD + ks * 16, PAD);
                #pragma unroll
                for (int i = 0; i < 4; i++) wmma::mma_sync(acc[i][j], a[i], bh, acc[i][j]);
                #pragma unroll
                for (int i = 0; i < 4; i++) wmma::mma_sync(acc[i][j], a[i], bl, acc[i][j]);
            }
        }
        __syncthreads();
    }

    // epilogue
    float* stg = (float*)smraw + (size_t)wid * (64 * 32);
    #pragma unroll
    for (int i = 0; i < 4; i++)
        #pragma unroll
        for (int j = 0; j < 2; j++)
            wmma::store_matrix_sync(stg + i * 16 * 32 + j * 16, acc[i][j], 32, wmma::mem_row_major);
    __syncwarp();

    const int nw0 = n0 + wn * 32;
    #pragma unroll
    for (int l = 0; l < 16; l++) {
        int idx = lane + l * 32;
        int r   = idx >> 3;
        int c4  = (idx & 7) * 4;
        float4 v = *(const float4*)(stg + r * 32 + c4);
        float4 bv = *(const float4*)&bias[nw0 + c4];
        v.x += bv.x; v.y += bv.y; v.z += bv.z; v.w += bv.w;
        const int m = m0 + wm * 64 + r;
        if (MODE == 0) {
            const int b = m >> 11, sq = m & 2047;
            const int hd = nw0 >> 6, d0 = (nw0 & 63) + c4;
            const size_t o = ((((size_t)b * HH + hd) * SS) + sq) * DD + d0;
            const float sc = (z == 0) ? 0.125f : 1.0f;
            __half* dst = (z == 0) ? g_qh : (z == 1) ? g_kh : g_vh;
            *(__half2*)(dst + o)     = __floats2half2_rn(v.x * sc, v.y * sc);
            *(__half2*)(dst + o + 2) = __floats2half2_rn(v.z * sc, v.w * sc);
        } else {
            *(float4*)&outp[(size_t)m * 1024 + nw0 + c4] = v;
        }
    }
}

// ---------------- WMMA fp16 flash attention, double-buffered K/V ----------------
#define KT_LD 72
#define KT_E  (64 * KT_LD)              // 4608 halves per tile
#define F_LD  68
#define ATTN_SMEM (2 * KT_E * 2 /*Q+P*/ + 4 * KT_E * 2 /*K[2],V[2]*/ + 2 * 64 * F_LD * 4)  // 90112

__global__ __launch_bounds__(128)
void attn3()
{
    extern __shared__ char smraw[];
    __half* sQ = (__half*)smraw;
    __half* sK = sQ + KT_E;              // [2][KT_E]
    __half* sV = sK + 2 * KT_E;          // [2][KT_E]
    __half* sP = sV + 2 * KT_E;
    float* sS = (float*)(sP + KT_E);
    float* sO = sS + 64 * F_LD;

    const int tid  = threadIdx.x;
    const int warp = tid >> 5;
    const int qt = blockIdx.x, hh = blockIdx.y, bb = blockIdx.z;
    const int row  = tid >> 1;
    const int half = tid & 1;
    const size_t hbase = (((size_t)bb * HH + hh) * SS) * DD;

    // Q group
    {
        const __half* qtile = g_qh + hbase + (size_t)qt * 64 * DD;
        #pragma unroll
        for (int i = 0; i < 4; i++) {
            int u = i * 128 + tid;
            int r = u >> 3, sg = u & 7;
            CP_ASYNC16(smem_u32(sQ + r * KT_LD + sg * 8), qtile + r * 64 + sg * 8);
        }
        CP_ASYNC_COMMIT();
    }
    // kt=0 K/V group into buffer 0
    {
        const __half* kt0 = g_kh + hbase;
        const __half* vt0 = g_vh + hbase;
        #pragma unroll
        for (int i = 0; i < 4; i++) {
            int u = i * 128 + tid;
            int r = u >> 3, sg = u & 7;
            int so = r * KT_LD + sg * 8, go = r * 64 + sg * 8;
            CP_ASYNC16(smem_u32(sK + so), kt0 + go);
            CP_ASYNC16(smem_u32(sV + so), vt0 + go);
        }
        CP_ASYNC_COMMIT();
    }

    for (int i = tid; i < 64 * F_LD; i += 128) sO[i] = 0.0f;

    CP_ASYNC_WAIT1();   // Q done (kt=0 group may still fly)
    __syncthreads();

    wmma::fragment<wmma::matrix_a, 16, 16, 16, __half, wmma::row_major> aQ[4];
    #pragma unroll
    for (int kk = 0; kk < 4; kk++)
        wmma::load_matrix_sync(aQ[kk], sQ + (size_t)(warp * 16) * KT_LD + kk * 16, KT_LD);

    float m_i = -INFINITY, l_i = 0.0f;

    for (int kt = 0; kt <= qt; kt++) {
        __syncthreads();   // prior iteration's reads of this buffer + sS/sP done
        if (kt < qt) {     // prefetch kt+1 into other buffer
            const __half* kn = g_kh + hbase + (size_t)(kt + 1) * 64 * DD;
            const __half* vn = g_vh + hbase + (size_t)(kt + 1) * 64 * DD;
            __half* dK = sK + ((kt + 1) & 1) * KT_E;
            __half* dV = sV + ((kt + 1) & 1) * KT_E;
            #pragma unroll
            for (int i = 0; i < 4; i++) {
                int u = i * 128 + tid;
                int r = u >> 3, sg = u & 7;
                int so = r * KT_LD + sg * 8, go = r * 64 + sg * 8;
                CP_ASYNC16(smem_u32(dK + so), kn + go);
                CP_ASYNC16(smem_u32(dV + so), vn + go);
            }
            CP_ASYNC_COMMIT();
            CP_ASYNC_WAIT1();
        } else {
            CP_ASYNC_WAIT0();
        }
        __syncthreads();

        const __half* cK = sK + (kt & 1) * KT_E;
        const __half* cV = sV + (kt & 1) * KT_E;

        // ---- scores ----
        {
            wmma::fragment<wmma::accumulator, 16, 16, 16, float> accS[4];
            #pragma unroll
            for (int j = 0; j < 4; j++) wmma::fill_fragment(accS[j], 0.0f);
            #pragma unroll
            for (int kk = 0; kk < 4; kk++) {
                #pragma unroll
                for (int j = 0; j < 4; j++) {
                    wmma::fragment<wmma::matrix_b, 16, 16, 16, __half, wmma::col_major> bK;
                    wmma::load_matrix_sync(bK, cK + (size_t)(j * 16) * KT_LD + kk * 16, KT_LD);
                    wmma::mma_sync(accS[j], aQ[kk], bK, accS[j]);
                }
            }
            #pragma unroll
            for (int j = 0; j < 4; j++)
                wmma::store_matrix_sync(sS + (size_t)(warp * 16) * F_LD + j * 16, accS[j], F_LD, wmma::mem_row_major);
        }
        __syncthreads();

        // ---- softmax (2 threads per row) ----
        {
            const float* srow = sS + (size_t)row * F_LD + half * 32;
            const bool diag = (kt == qt);
            float mx = -INFINITY;
            #pragma unroll
            for (int c8 = 0; c8 < 8; c8++) {
                float4 v = *(const float4*)(srow + 4 * c8);
                if (diag) {
                    int c0 = half * 32 + 4 * c8;
                    if (c0 + 0 > row) v.x = -INFINITY;
                    if (c0 + 1 > row) v.y = -INFINITY;
                    if (c0 + 2 > row) v.z = -INFINITY;
                    if (c0 + 3 > row) v.w = -INFINITY;
                }
                mx = fmaxf(mx, fmaxf(fmaxf(v.x, v.y), fmaxf(v.z, v.w)));
            }
            mx = fmaxf(mx, __shfl_xor_sync(0xffffffffu, mx, 1));
            const float m_new = fmaxf(m_i, mx);
            const float alpha = __expf(m_i - m_new);
            float ps = 0.0f;
            __half* ph = sP + (size_t)row * KT_LD + half * 32;
            #pragma unroll
            for (int c8 = 0; c8 < 8; c8++) {
                float4 v = *(const float4*)(srow + 4 * c8);
                int c0 = half * 32 + 4 * c8;
                float p0 = (diag && c0 + 0 > row) ? 0.0f : __expf(v.x - m_new);
                float p1 = (diag && c0 + 1 > row) ? 0.0f : __expf(v.y - m_new);
                float p2 = (diag && c0 + 2 > row) ? 0.0f : __expf(v.z - m_new);
                float p3 = (diag && c0 + 3 > row) ? 0.0f : __expf(v.w - m_new);
                ps += p0 + p1 + p2 + p3;
                *(__half2*)(ph + 4*c8)     = __floats2half2_rn(p0, p1);
                *(__half2*)(ph + 4*c8 + 2) = __floats2half2_rn(p2, p3);
            }
            ps += __shfl_xor_sync(0xffffffffu, ps, 1);
            l_i = l_i * alpha + ps;
            m_i = m_new;
            float* orow = sO + (size_t)row * F_LD + half * 32;
            #pragma unroll
            for (int c8 = 0; c8 < 8; c8++) {
                float4 ov = *(const float4*)(orow + 4 * c8);
                ov.x *= alpha; ov.y *= alpha; ov.z *= alpha; ov.w *= alpha;
                *(float4*)(orow + 4 * c8) = ov;
            }
        }
        __syncthreads();

        // ---- PV ----
        {
            wmma::fragment<wmma::accumulator, 16, 16, 16, float> accO[4];
            #pragma unroll
            for (int j = 0; j < 4; j++) wmma::fill_fragment(accO[j], 0.0f);
            #pragma unroll
            for (int kk = 0; kk < 4; kk++) {
                wmma::fragment<wmma::matrix_a, 16, 16, 16, __half, wmma::row_major> aP;
                wmma::load_matrix_sync(aP, sP + (size_t)(warp * 16) * KT_LD + kk * 16, KT_LD);
                #pragma unroll
                for (int j = 0; j < 4; j++) {
                    wmma::fragment<wmma::matrix_b, 16, 16, 16, __half, wmma::row_major> bV;
                    wmma::load_matrix_sync(bV, cV + (size_t)(kk * 16) * KT_LD + j * 16, KT_LD);
                    wmma::mma_sync(accO[j], aP, bV, accO[j]);
                }
            }
            #pragma unroll
            for (int j = 0; j < 4; j++)
                wmma::store_matrix_sync(sS + (size_t)(warp * 16) * F_LD + j * 16, accO[j], F_LD, wmma::mem_row_major);
        }
        __syncthreads();

        // ---- O += delta ----
        {
            const float* drow = sS + (size_t)row * F_LD + half * 32;
            float* orow = sO + (size_t)row * F_LD + half * 32;
            #pragma unroll
            for (int c8 = 0; c8 < 8; c8++) {
                float4 d = *(const float4*)(drow + 4 * c8);
                float4 o = *(const float4*)(orow + 4 * c8);
                o.x += d.x; o.y += d.y; o.z += d.z; o.w += d.w;
                *(float4*)(orow + 4 * c8) = o;
            }
        }
    }

    // epilogue: normalize + write fp16 A-operand for O projection ([B,S,E] row-major)
    {
        const float inv = 1.0f / l_i;
        const float* orow = sO + (size_t)row * F_LD + half * 32;
        const size_t go = ((size_t)bb * SS + (size_t)qt * 64 + row) * EE + hh * DD + half * 32;
        #pragma unroll
        for (int c8 = 0; c8 < 8; c8++) {
            float4 v = *(const float4*)(orow + 4 * c8);
            *(__half2*)(g_xh + go + 4*c8)     = __floats2half2_rn(v.x * inv, v.y * inv);
            *(__half2*)(g_xh + go + 4*c8 + 2) = __floats2half2_rn(v.z * inv, v.w * inv);
        }
    }
}

// ---------------------------------------------------------------------------
extern "C" void kernel_launch(void* const* d_in, const int* in_sizes, int n_in,
                              void* d_out, int out_size)
{
    const float* x  = (const float*)d_in[0];
    const float* Wq = (const float*)d_in[1];
    const float* bq = (const float*)d_in[2];
    const float* Wk = (const float*)d_in[3];
    const float* bk = (const float*)d_in[4];
    const float* Wv = (const float*)d_in[5];
    const float* bv = (const float*)d_in[6];
    const float* Wo = (const float*)d_in[7];
    const float* bo = (const float*)d_in[8];
    float* out = (float*)d_out;

    cudaFuncSetAttribute(wgemm<0>, cudaFuncAttributeMaxDynamicSharedMemorySize, GEMM_SMEM);
    cudaFuncSetAttribute(wgemm<1>, cudaFuncAttributeMaxDynamicSharedMemorySize, GEMM_SMEM);
    cudaFuncSetAttribute(attn3,    cudaFuncAttributeMaxDynamicSharedMemorySize, ATTN_SMEM);

    const dim3 wg(32, 32);

    conv_x<<<MM * EE / 2048, 256>>>(x);
    conv_w<<<wg, 256>>>(Wq, 0);
    conv_w<<<wg, 256>>>(Wk, 1);
    conv_w<<<wg, 256>>>(Wv, 2);
    conv_w<<<wg, 256>>>(Wo, 3);

    wgemm<0><<<dim3(EE / 128, MM / 128, 3), 256, GEMM_SMEM>>>(bq, bk, bv, nullptr);

    attn3<<<dim3(SS / 64, HH, BB), 128, ATTN_SMEM>>>();

    wgemm<1><<<dim3(EE / 128, MM / 128, 1), 256, GEMM_SMEM>>>(bo, nullptr, nullptr, out);
}

// round 8
// speedup vs baseline: 1.8943x; 1.4165x over previous
#include <cuda_runtime.h>
#include <cuda_fp16.h>
#include <mma.h>
#include <cstdint>
#include <math.h>

using namespace nvcuda;

#define BB 4
#define SS 2048
#define EE 1024
#define HH 16
#define DD 64
#define MM (BB*SS)   // 8192

// ---------------- device scratch (allocation-free contract) ----------------
__device__ __align__(16) __half g_xh[(size_t)MM*EE];        // A operand fp16 [M,K]; attn writes O here
__device__ __align__(16) __half g_wth[4*(size_t)EE*EE];     // W^T hi [slot][N,K]
__device__ __align__(16) __half g_wtl[4*(size_t)EE*EE];     // W^T lo (only slots 2,3 used)
__device__ __align__(16) __half g_qh[(size_t)BB*HH*SS*DD];  // Q fp16 (pre-scaled 1/8), [B,H,S,D]
__device__ __align__(16) __half g_kh[(size_t)BB*HH*SS*DD];  // K fp16
__device__ __align__(16) __half g_vh[(size_t)BB*HH*SS*DD];  // V fp16

// ---------------- helpers ----------------
__device__ __forceinline__ uint32_t smem_u32(const void* p) {
    uint32_t a;
    asm("{ .reg .u64 t; cvta.to.shared.u64 t, %1; cvt.u32.u64 %0, t; }" : "=r"(a) : "l"(p));
    return a;
}
#define CP_ASYNC16(sa, g)  asm volatile("cp.async.cg.shared.global [%0], [%1], 16;" :: "r"(sa), "l"(g) : "memory")
#define CP_ASYNC_COMMIT()  asm volatile("cp.async.commit_group;" ::: "memory")
#define CP_ASYNC_WAIT0()   asm volatile("cp.async.wait_group 0;" ::: "memory")
#define CP_ASYNC_WAIT1()   asm volatile("cp.async.wait_group 1;" ::: "memory")
#define CP_ASYNC_WAIT2()   asm volatile("cp.async.wait_group 2;" ::: "memory")

__device__ __forceinline__ void split2h(float v, __half& h, __half& l) {
    h = __float2half_rn(v);
    l = __float2half_rn(v - __half2float(h));
}

// ---------------- converters ----------------
__global__ __launch_bounds__(256) void conv_x(const float* __restrict__ in) {
    size_t i = ((size_t)blockIdx.x * 256 + threadIdx.x) * 8;
    float4 a = *(const float4*)(in + i);
    float4 b = *(const float4*)(in + i + 4);
    __half2 o[4];
    o[0] = __floats2half2_rn(a.x, a.y);
    o[1] = __floats2half2_rn(a.z, a.w);
    o[2] = __floats2half2_rn(b.x, b.y);
    o[3] = __floats2half2_rn(b.z, b.w);
    *(uint4*)(g_xh + i) = *(uint4*)o;
}

// fused: z=0 Wq, z=1 Wk (hi only), z=2 Wv (hi+lo)
__global__ __launch_bounds__(256) void conv_w3(const float* __restrict__ W0,
                                               const float* __restrict__ W1,
                                               const float* __restrict__ W2) {
    __shared__ float t[32][33];
    const int tx = threadIdx.x & 31, ty = threadIdx.x >> 5;
    const int n0 = blockIdx.x * 32, k0 = blockIdx.y * 32;
    const int z = blockIdx.z;
    const float* W = (z == 0) ? W0 : (z == 1) ? W1 : W2;
    __half* wh = g_wth + (size_t)z * EE * EE;
    __half* wl = g_wtl + (size_t)z * EE * EE;
    #pragma unroll
    for (int j = 0; j < 4; j++)
        t[ty + 8*j][tx] = W[(size_t)(k0 + ty + 8*j) * 1024 + n0 + tx];
    __syncthreads();
    #pragma unroll
    for (int j = 0; j < 4; j++) {
        float v = t[tx][ty + 8*j];
        size_t o = (size_t)(n0 + ty + 8*j) * 1024 + k0 + tx;
        if (z == 2) {
            __half hh, ll; split2h(v, hh, ll);
            wh[o] = hh; wl[o] = ll;
        } else {
            wh[o] = __float2half_rn(v);
        }
    }
}

__global__ __launch_bounds__(256) void conv_w(const float* __restrict__ W, int widx) {
    __shared__ float t[32][33];
    const int tx = threadIdx.x & 31, ty = threadIdx.x >> 5;
    const int n0 = blockIdx.x * 32, k0 = blockIdx.y * 32;
    __half* wh = g_wth + (size_t)widx * EE * EE;
    __half* wl = g_wtl + (size_t)widx * EE * EE;
    #pragma unroll
    for (int j = 0; j < 4; j++)
        t[ty + 8*j][tx] = W[(size_t)(k0 + ty + 8*j) * 1024 + n0 + tx];
    __syncthreads();
    #pragma unroll
    for (int j = 0; j < 4; j++) {
        float v = t[tx][ty + 8*j];
        __half hh, ll; split2h(v, hh, ll);
        size_t o = (size_t)(n0 + ty + 8*j) * 1024 + k0 + tx;
        wh[o] = hh;
        wl[o] = ll;
    }
}

// ---------------- WMMA GEMM, 3-stage cp.async pipeline ----------------
#define PAD 40
#define TILE_B   (128 * PAD * 2)        // 10240 B
#define TILE_E   (128 * PAD)
#define STAGE_B  (3 * TILE_B)           // 30720: A, Bh, Bl
#define STAGE_E  (3 * TILE_E)
#define GEMM_SMEM (3 * STAGE_B)         // 92160 (also covers epilogue 65536)

__device__ __forceinline__ void stage_load(uint32_t sb,
    const __half* A, const __half* Bh, const __half* Bl, int k0, int tid, bool lo)
{
    #pragma unroll
    for (int t = 0; t < 2; t++) {
        int u   = tid + t * 256;
        int row = u >> 2;
        int seg = u & 3;
        uint32_t off = (uint32_t)row * (PAD * 2) + seg * 16;
        size_t g = (size_t)row * 1024 + k0 + seg * 8;
        CP_ASYNC16(sb + off,          A  + g);
        CP_ASYNC16(sb + TILE_B + off, Bh + g);
        if (lo) CP_ASYNC16(sb + 2 * TILE_B + off, Bl + g);
    }
}

// MODE 0: fused QKV (z = 0/1/2; z<2 single-term B)
// MODE 1: O projection (slot 3, 2-term, fp32 out)
template<int MODE>
__global__ __launch_bounds__(256)
void wgemm(const float* __restrict__ bias0, const float* __restrict__ bias1,
           const float* __restrict__ bias2, float* __restrict__ outp)
{
    extern __shared__ char smraw[];
    __half* s = (__half*)smraw;
    const uint32_t sbase = smem_u32(smraw);

    const int tid  = threadIdx.x;
    const int wid  = tid >> 5, lane = tid & 31;
    const int wm   = wid >> 2, wn = wid & 3;
    const int m0   = blockIdx.y * 128;
    const int n0   = blockIdx.x * 128;
    const int z    = (MODE == 0) ? blockIdx.z : 3;
    const bool use_lo = (MODE == 1) || (z == 2);
    const float* bias = (MODE == 1) ? bias0 : (z == 0 ? bias0 : z == 1 ? bias1 : bias2);

    const __half* A  = g_xh + (size_t)m0 * 1024;
    const __half* Bh = g_wth + (size_t)z * EE * EE + (size_t)n0 * 1024;
    const __half* Bl = g_wtl + (size_t)z * EE * EE + (size_t)n0 * 1024;

    wmma::fragment<wmma::accumulator, 16, 16, 16, float> acc[4][2];
    #pragma unroll
    for (int i = 0; i < 4; i++)
        #pragma unroll
        for (int j = 0; j < 2; j++) wmma::fill_fragment(acc[i][j], 0.0f);

    stage_load(sbase,           A, Bh, Bl, 0,  tid, use_lo); CP_ASYNC_COMMIT();
    stage_load(sbase + STAGE_B, A, Bh, Bl, 32, tid, use_lo); CP_ASYNC_COMMIT();

    for (int kc = 0; kc < 32; kc++) {
        if (kc + 2 < 32) {
            stage_load(sbase + ((kc + 2) % 3) * STAGE_B, A, Bh, Bl, (kc + 2) * 32, tid, use_lo);
            CP_ASYNC_COMMIT();
            CP_ASYNC_WAIT2();
        } else if (kc + 2 == 32) {
            CP_ASYNC_WAIT1();
        } else {
            CP_ASYNC_WAIT0();
        }
        __syncthreads();

        const __half* st  = s + (kc % 3) * STAGE_E;
        const __half* sa  = st;
        const __half* sbh = st + TILE_E;
        const __half* sbl = st + 2 * TILE_E;

        #pragma unroll
        for (int ks = 0; ks < 2; ks++) {
            wmma::fragment<wmma::matrix_a, 16, 16, 16, __half, wmma::row_major> a[4];
            #pragma unroll
            for (int i = 0; i < 4; i++)
                wmma::load_matrix_sync(a[i], sa + (size_t)(wm * 64 + i * 16) * PAD + ks * 16, PAD);
            #pragma unroll
            for (int j = 0; j < 2; j++) {
                wmma::fragment<wmma::matrix_b, 16, 16, 16, __half, wmma::col_major> bh;
                wmma::load_matrix_sync(bh, sbh + (size_t)(wn * 32 + j * 16) * PAD + ks * 16, PAD);
                #pragma unroll
                for (int i = 0; i < 4; i++) wmma::mma_sync(acc[i][j], a[i], bh, acc[i][j]);
                if (use_lo) {
                    wmma::fragment<wmma::matrix_b, 16, 16, 16, __half, wmma::col_major> bl;
                    wmma::load_matrix_sync(bl, sbl + (size_t)(wn * 32 + j * 16) * PAD + ks * 16, PAD);
                    #pragma unroll
                    for (int i = 0; i < 4; i++) wmma::mma_sync(acc[i][j], a[i], bl, acc[i][j]);
                }
            }
        }
        __syncthreads();
    }

    // epilogue
    float* stg = (float*)smraw + (size_t)wid * (64 * 32);
    #pragma unroll
    for (int i = 0; i < 4; i++)
        #pragma unroll
        for (int j = 0; j < 2; j++)
            wmma::store_matrix_sync(stg + i * 16 * 32 + j * 16, acc[i][j], 32, wmma::mem_row_major);
    __syncwarp();

    const int nw0 = n0 + wn * 32;
    #pragma unroll
    for (int l = 0; l < 16; l++) {
        int idx = lane + l * 32;
        int r   = idx >> 3;
        int c4  = (idx & 7) * 4;
        float4 v = *(const float4*)(stg + r * 32 + c4);
        float4 bv = *(const float4*)&bias[nw0 + c4];
        v.x += bv.x; v.y += bv.y; v.z += bv.z; v.w += bv.w;
        const int m = m0 + wm * 64 + r;
        if (MODE == 0) {
            const int b = m >> 11, sq = m & 2047;
            const int hd = nw0 >> 6, d0 = (nw0 & 63) + c4;
            const size_t o = ((((size_t)b * HH + hd) * SS) + sq) * DD + d0;
            const float sc = (z == 0) ? 0.125f : 1.0f;
            __half* dst = (z == 0) ? g_qh : (z == 1) ? g_kh : g_vh;
            *(__half2*)(dst + o)     = __floats2half2_rn(v.x * sc, v.y * sc);
            *(__half2*)(dst + o + 2) = __floats2half2_rn(v.z * sc, v.w * sc);
        } else {
            *(float4*)&outp[(size_t)m * 1024 + nw0 + c4] = v;
        }
    }
}

// ---------------- WMMA fp16 flash attention, register O accumulator ----------------
#define KT_LD 72
#define KT_E  (64 * KT_LD)
#define F_LD  68
#define ATTN_SMEM (6 * KT_E * 2 + (64 * F_LD + 128) * 4)   // 73216

__global__ __launch_bounds__(128)
void attn3()
{
    extern __shared__ char smraw[];
    __half* sQ = (__half*)smraw;
    __half* sK = sQ + KT_E;              // [2][KT_E]
    __half* sV = sK + 2 * KT_E;          // [2][KT_E]
    __half* sP = sV + 2 * KT_E;
    float* sS     = (float*)(sP + KT_E);
    float* salpha = sS + 64 * F_LD;
    float* slinv  = salpha + 64;

    const int tid  = threadIdx.x;
    const int warp = tid >> 5;
    const int qt = blockIdx.x, hh = blockIdx.y, bb = blockIdx.z;
    const int row  = tid >> 1;
    const int half = tid & 1;
    const size_t hbase = (((size_t)bb * HH + hh) * SS) * DD;

    // Q group
    {
        const __half* qtile = g_qh + hbase + (size_t)qt * 64 * DD;
        #pragma unroll
        for (int i = 0; i < 4; i++) {
            int u = i * 128 + tid;
            int r = u >> 3, sg = u & 7;
            CP_ASYNC16(smem_u32(sQ + r * KT_LD + sg * 8), qtile + r * 64 + sg * 8);
        }
        CP_ASYNC_COMMIT();
    }
    // kt=0 K/V group into buffer 0
    {
        const __half* kt0 = g_kh + hbase;
        const __half* vt0 = g_vh + hbase;
        #pragma unroll
        for (int i = 0; i < 4; i++) {
            int u = i * 128 + tid;
            int r = u >> 3, sg = u & 7;
            int so = r * KT_LD + sg * 8, go = r * 64 + sg * 8;
            CP_ASYNC16(smem_u32(sK + so), kt0 + go);
            CP_ASYNC16(smem_u32(sV + so), vt0 + go);
        }
        CP_ASYNC_COMMIT();
    }

    // accumulator-layout discovery: fill 16x16 row-index matrix, load into acc frag
    for (int i = tid; i < 256; i += 128)
        sS[(i >> 4) * F_LD + (i & 15)] = (float)(i >> 4);
    __syncthreads();
    int rowidx[8];
    {
        wmma::fragment<wmma::accumulator, 16, 16, 16, float> rfrag;
        wmma::load_matrix_sync(rfrag, sS, F_LD, wmma::mem_row_major);
        #pragma unroll
        for (int i = 0; i < 8; i++) rowidx[i] = (int)rfrag.x[i];
    }

    CP_ASYNC_WAIT1();   // Q done
    __syncthreads();    // rfrag loads done before sS reuse; Q visible to all

    wmma::fragment<wmma::matrix_a, 16, 16, 16, __half, wmma::row_major> aQ[4];
    #pragma unroll
    for (int kk = 0; kk < 4; kk++)
        wmma::load_matrix_sync(aQ[kk], sQ + (size_t)(warp * 16) * KT_LD + kk * 16, KT_LD);

    wmma::fragment<wmma::accumulator, 16, 16, 16, float> accO[4];
    #pragma unroll
    for (int j = 0; j < 4; j++) wmma::fill_fragment(accO[j], 0.0f);

    float m_i = -INFINITY, l_i = 0.0f;

    for (int kt = 0; kt <= qt; kt++) {
        __syncthreads();   // prior reads of target K/V buffer + sS done
        if (kt < qt) {
            const __half* kn = g_kh + hbase + (size_t)(kt + 1) * 64 * DD;
            const __half* vn = g_vh + hbase + (size_t)(kt + 1) * 64 * DD;
            __half* dK = sK + ((kt + 1) & 1) * KT_E;
            __half* dV = sV + ((kt + 1) & 1) * KT_E;
            #pragma unroll
            for (int i = 0; i < 4; i++) {
                int u = i * 128 + tid;
                int r = u >> 3, sg = u & 7;
                int so = r * KT_LD + sg * 8, go = r * 64 + sg * 8;
                CP_ASYNC16(smem_u32(dK + so), kn + go);
                CP_ASYNC16(smem_u32(dV + so), vn + go);
            }
            CP_ASYNC_COMMIT();
            CP_ASYNC_WAIT1();
        } else {
            CP_ASYNC_WAIT0();
        }
        __syncthreads();

        const __half* cK = sK + (kt & 1) * KT_E;
        const __half* cV = sV + (kt & 1) * KT_E;

        // ---- scores (warp-private sS region) ----
        {
            wmma::fragment<wmma::accumulator, 16, 16, 16, float> accS[4];
            #pragma unroll
            for (int j = 0; j < 4; j++) wmma::fill_fragment(accS[j], 0.0f);
            #pragma unroll
            for (int kk = 0; kk < 4; kk++) {
                #pragma unroll
                for (int j = 0; j < 4; j++) {
                    wmma::fragment<wmma::matrix_b, 16, 16, 16, __half, wmma::col_major> bK;
                    wmma::load_matrix_sync(bK, cK + (size_t)(j * 16) * KT_LD + kk * 16, KT_LD);
                    wmma::mma_sync(accS[j], aQ[kk], bK, accS[j]);
                }
            }
            #pragma unroll
            for (int j = 0; j < 4; j++)
                wmma::store_matrix_sync(sS + (size_t)(warp * 16) * F_LD + j * 16, accS[j], F_LD, wmma::mem_row_major);
        }
        __syncwarp();

        // ---- softmax (2 threads per row; rows are warp-private) ----
        {
            const float* srow = sS + (size_t)row * F_LD + half * 32;
            const bool diag = (kt == qt);
            float mx = -INFINITY;
            #pragma unroll
            for (int c8 = 0; c8 < 8; c8++) {
                float4 v = *(const float4*)(srow + 4 * c8);
                if (diag) {
                    int c0 = half * 32 + 4 * c8;
                    if (c0 + 0 > row) v.x = -INFINITY;
                    if (c0 + 1 > row) v.y = -INFINITY;
                    if (c0 + 2 > row) v.z = -INFINITY;
                    if (c0 + 3 > row) v.w = -INFINITY;
                }
                mx = fmaxf(mx, fmaxf(fmaxf(v.x, v.y), fmaxf(v.z, v.w)));
            }
            mx = fmaxf(mx, __shfl_xor_sync(0xffffffffu, mx, 1));
            const float m_new = fmaxf(m_i, mx);
            const float alpha = __expf(m_i - m_new);
            float ps = 0.0f;
            __half* ph = sP + (size_t)row * KT_LD + half * 32;
            #pragma unroll
            for (int c8 = 0; c8 < 8; c8++) {
                float4 v = *(const float4*)(srow + 4 * c8);
                int c0 = half * 32 + 4 * c8;
                float p0 = (diag && c0 + 0 > row) ? 0.0f : __expf(v.x - m_new);
                float p1 = (diag && c0 + 1 > row) ? 0.0f : __expf(v.y - m_new);
                float p2 = (diag && c0 + 2 > row) ? 0.0f : __expf(v.z - m_new);
                float p3 = (diag && c0 + 3 > row) ? 0.0f : __expf(v.w - m_new);
                ps += p0 + p1 + p2 + p3;
                *(__half2*)(ph + 4*c8)     = __floats2half2_rn(p0, p1);
                *(__half2*)(ph + 4*c8 + 2) = __floats2half2_rn(p2, p3);
            }
            ps += __shfl_xor_sync(0xffffffffu, ps, 1);
            l_i = l_i * alpha + ps;
            m_i = m_new;
            if (half == 0) salpha[row] = alpha;
        }
        __syncwarp();

        // ---- PV: rescale accO in registers, then accumulate ----
        {
            float av[8];
            #pragma unroll
            for (int i = 0; i < 8; i++) av[i] = salpha[warp * 16 + rowidx[i]];
            #pragma unroll
            for (int j = 0; j < 4; j++)
                #pragma unroll
                for (int i = 0; i < 8; i++) accO[j].x[i] *= av[i];

            #pragma unroll
            for (int kk = 0; kk < 4; kk++) {
                wmma::fragment<wmma::matrix_a, 16, 16, 16, __half, wmma::row_major> aP;
                wmma::load_matrix_sync(aP, sP + (size_t)(warp * 16) * KT_LD + kk * 16, KT_LD);
                #pragma unroll
                for (int j = 0; j < 4; j++) {
                    wmma::fragment<wmma::matrix_b, 16, 16, 16, __half, wmma::row_major> bV;
                    wmma::load_matrix_sync(bV, cV + (size_t)(kk * 16) * KT_LD + j * 16, KT_LD);
                    wmma::mma_sync(accO[j], aP, bV, accO[j]);
                }
            }
        }
    }

    // epilogue: normalize in-register, stage via sS (warp-private), write fp16
    if (half == 0) slinv[row] = 1.0f / l_i;
    __syncwarp();
    {
        float nv[8];
        #pragma unroll
        for (int i = 0; i < 8; i++) nv[i] = slinv[warp * 16 + rowidx[i]];
        #pragma unroll
        for (int j = 0; j < 4; j++)
            #pragma unroll
            for (int i = 0; i < 8; i++) accO[j].x[i] *= nv[i];
        #pragma unroll
        for (int j = 0; j < 4; j++)
            wmma::store_matrix_sync(sS + (size_t)(warp * 16) * F_LD + j * 16, accO[j], F_LD, wmma::mem_row_major);
    }
    __syncwarp();
    {
        const float* orow = sS + (size_t)row * F_LD + half * 32;
        const size_t go = ((size_t)bb * SS + (size_t)qt * 64 + row) * EE + hh * DD + half * 32;
        #pragma unroll
        for (int c8 = 0; c8 < 8; c8++) {
            float4 v = *(const float4*)(orow + 4 * c8);
            *(__half2*)(g_xh + go + 4*c8)     = __floats2half2_rn(v.x, v.y);
            *(__half2*)(g_xh + go + 4*c8 + 2) = __floats2half2_rn(v.z, v.w);
        }
    }
}

// ---------------------------------------------------------------------------
extern "C" void kernel_launch(void* const* d_in, const int* in_sizes, int n_in,
                              void* d_out, int out_size)
{
    const float* x  = (const float*)d_in[0];
    const float* Wq = (const float*)d_in[1];
    const float* bq = (const float*)d_in[2];
    const float* Wk = (const float*)d_in[3];
    const float* bk = (const float*)d_in[4];
    const float* Wv = (const float*)d_in[5];
    const float* bv = (const float*)d_in[6];
    const float* Wo = (const float*)d_in[7];
    const float* bo = (const float*)d_in[8];
    float* out = (float*)d_out;

    cudaFuncSetAttribute(wgemm<0>, cudaFuncAttributeMaxDynamicSharedMemorySize, GEMM_SMEM);
    cudaFuncSetAttribute(wgemm<1>, cudaFuncAttributeMaxDynamicSharedMemorySize, GEMM_SMEM);
    cudaFuncSetAttribute(attn3,    cudaFuncAttributeMaxDynamicSharedMemorySize, ATTN_SMEM);

    // attn3 is the 5th launch (the slot ncu captures)
    conv_x<<<MM * EE / 2048, 256>>>(x);
    conv_w3<<<dim3(32, 32, 3), 256>>>(Wq, Wk, Wv);
    wgemm<0><<<dim3(EE / 128, MM / 128, 3), 256, GEMM_SMEM>>>(bq, bk, bv, nullptr);
    conv_w<<<dim3(32, 32), 256>>>(Wo, 3);
    attn3<<<dim3(SS / 64, HH, BB), 128, ATTN_SMEM>>>();
    wgemm<1><<<dim3(EE / 128, MM / 128, 1), 256, GEMM_SMEM>>>(bo, nullptr, nullptr, out);
}

// round 9
// speedup vs baseline: 2.3189x; 1.2241x over previous
#include <cuda_runtime.h>
#include <cuda_fp16.h>
#include <mma.h>
#include <cstdint>
#include <math.h>

using namespace nvcuda;

#define BB 4
#define SS 2048
#define EE 1024
#define HH 16
#define DD 64
#define MM (BB*SS)   // 8192

// ---------------- device scratch (allocation-free contract) ----------------
__device__ __align__(16) __half g_xh[(size_t)MM*EE];        // A operand fp16 [M,K]; attn writes O here
__device__ __align__(16) __half g_wth[4*(size_t)EE*EE];     // W^T hi [slot][N,K]
__device__ __align__(16) __half g_wtl[4*(size_t)EE*EE];     // W^T lo (slot 3 only)
__device__ __align__(16) __half g_qh[(size_t)BB*HH*SS*DD];  // Q fp16 (pre-scaled 1/8)
__device__ __align__(16) __half g_kh[(size_t)BB*HH*SS*DD];  // K fp16
__device__ __align__(16) __half g_vh[(size_t)BB*HH*SS*DD];  // V fp16

// ---------------- helpers ----------------
__device__ __forceinline__ uint32_t smem_u32(const void* p) {
    uint32_t a;
    asm("{ .reg .u64 t; cvta.to.shared.u64 t, %1; cvt.u32.u64 %0, t; }" : "=r"(a) : "l"(p));
    return a;
}
#define CP_ASYNC16(sa, g)  asm volatile("cp.async.cg.shared.global [%0], [%1], 16;" :: "r"(sa), "l"(g) : "memory")
#define CP_ASYNC_COMMIT()  asm volatile("cp.async.commit_group;" ::: "memory")
#define CP_ASYNC_WAIT0()   asm volatile("cp.async.wait_group 0;" ::: "memory")
#define CP_ASYNC_WAIT1()   asm volatile("cp.async.wait_group 1;" ::: "memory")
#define CP_ASYNC_WAIT2()   asm volatile("cp.async.wait_group 2;" ::: "memory")

__device__ __forceinline__ void split2h(float v, __half& h, __half& l) {
    h = __float2half_rn(v);
    l = __float2half_rn(v - __half2float(h));
}

// ---------------- converters ----------------
__global__ __launch_bounds__(256) void conv_x(const float* __restrict__ in) {
    size_t i = ((size_t)blockIdx.x * 256 + threadIdx.x) * 8;
    float4 a = *(const float4*)(in + i);
    float4 b = *(const float4*)(in + i + 4);
    __half2 o[4];
    o[0] = __floats2half2_rn(a.x, a.y);
    o[1] = __floats2half2_rn(a.z, a.w);
    o[2] = __floats2half2_rn(b.x, b.y);
    o[3] = __floats2half2_rn(b.z, b.w);
    *(uint4*)(g_xh + i) = *(uint4*)o;
}

// z=0..2: Wq/Wk/Wv single fp16; z=3: Wo hi+lo
__global__ __launch_bounds__(256) void conv_w4(const float* __restrict__ W0,
                                               const float* __restrict__ W1,
                                               const float* __restrict__ W2,
                                               const float* __restrict__ W3) {
    __shared__ float t[32][33];
    const int tx = threadIdx.x & 31, ty = threadIdx.x >> 5;
    const int n0 = blockIdx.x * 32, k0 = blockIdx.y * 32;
    const int z = blockIdx.z;
    const float* W = (z == 0) ? W0 : (z == 1) ? W1 : (z == 2) ? W2 : W3;
    __half* wh = g_wth + (size_t)z * EE * EE;
    __half* wl = g_wtl + (size_t)z * EE * EE;
    #pragma unroll
    for (int j = 0; j < 4; j++)
        t[ty + 8*j][tx] = W[(size_t)(k0 + ty + 8*j) * 1024 + n0 + tx];
    __syncthreads();
    #pragma unroll
    for (int j = 0; j < 4; j++) {
        float v = t[tx][ty + 8*j];
        size_t o = (size_t)(n0 + ty + 8*j) * 1024 + k0 + tx;
        if (z == 3) {
            __half hh, ll; split2h(v, hh, ll);
            wh[o] = hh; wl[o] = ll;
        } else {
            wh[o] = __float2half_rn(v);
        }
    }
}

// ---------------- WMMA GEMM, 3-stage cp.async pipeline ----------------
#define PAD 40
#define TILE_B   (128 * PAD * 2)
#define TILE_E   (128 * PAD)
#define STAGE_B  (3 * TILE_B)
#define STAGE_E  (3 * TILE_E)
#define GEMM_SMEM 92160

__device__ __forceinline__ void stage_load(uint32_t sb,
    const __half* A, const __half* Bh, const __half* Bl, int k0, int tid, bool lo)
{
    #pragma unroll
    for (int t = 0; t < 2; t++) {
        int u   = tid + t * 256;
        int row = u >> 2;
        int seg = u & 3;
        uint32_t off = (uint32_t)row * (PAD * 2) + seg * 16;
        size_t g = (size_t)row * 1024 + k0 + seg * 8;
        CP_ASYNC16(sb + off,          A  + g);
        CP_ASYNC16(sb + TILE_B + off, Bh + g);
        if (lo) CP_ASYNC16(sb + 2 * TILE_B + off, Bl + g);
    }
}

// MODE 0: fused QKV (z = 0/1/2, single-term)
// MODE 1: O projection (slot 3, 2-term, fp32 out)
template<int MODE>
__global__ __launch_bounds__(256)
void wgemm(const float* __restrict__ bias0, const float* __restrict__ bias1,
           const float* __restrict__ bias2, float* __restrict__ outp)
{
    extern __shared__ char smraw[];
    __half* s = (__half*)smraw;
    const uint32_t sbase = smem_u32(smraw);

    const int tid  = threadIdx.x;
    const int wid  = tid >> 5, lane = tid & 31;
    const int wm   = wid >> 2, wn = wid & 3;
    const int m0   = blockIdx.y * 128;
    const int n0   = blockIdx.x * 128;
    const int z    = (MODE == 0) ? blockIdx.z : 3;
    const bool use_lo = (MODE == 1);
    const float* bias = (MODE == 1) ? bias0 : (z == 0 ? bias0 : z == 1 ? bias1 : bias2);

    const __half* A  = g_xh + (size_t)m0 * 1024;
    const __half* Bh = g_wth + (size_t)z * EE * EE + (size_t)n0 * 1024;
    const __half* Bl = g_wtl + (size_t)z * EE * EE + (size_t)n0 * 1024;

    wmma::fragment<wmma::accumulator, 16, 16, 16, float> acc[4][2];
    #pragma unroll
    for (int i = 0; i < 4; i++)
        #pragma unroll
        for (int j = 0; j < 2; j++) wmma::fill_fragment(acc[i][j], 0.0f);

    stage_load(sbase,           A, Bh, Bl, 0,  tid, use_lo); CP_ASYNC_COMMIT();
    stage_load(sbase + STAGE_B, A, Bh, Bl, 32, tid, use_lo); CP_ASYNC_COMMIT();

    for (int kc = 0; kc < 32; kc++) {
        if (kc + 2 < 32) {
            stage_load(sbase + ((kc + 2) % 3) * STAGE_B, A, Bh, Bl, (kc + 2) * 32, tid, use_lo);
            CP_ASYNC_COMMIT();
            CP_ASYNC_WAIT2();
        } else if (kc + 2 == 32) {
            CP_ASYNC_WAIT1();
        } else {
            CP_ASYNC_WAIT0();
        }
        __syncthreads();

        const __half* st  = s + (kc % 3) * STAGE_E;
        const __half* sa  = st;
        const __half* sbh = st + TILE_E;
        const __half* sbl = st + 2 * TILE_E;

        #pragma unroll
        for (int ks = 0; ks < 2; ks++) {
            wmma::fragment<wmma::matrix_a, 16, 16, 16, __half, wmma::row_major> a[4];
            #pragma unroll
            for (int i = 0; i < 4; i++)
                wmma::load_matrix_sync(a[i], sa + (size_t)(wm * 64 + i * 16) * PAD + ks * 16, PAD);
            #pragma unroll
            for (int j = 0; j < 2; j++) {
                wmma::fragment<wmma::matrix_b, 16, 16, 16, __half, wmma::col_major> bh;
                wmma::load_matrix_sync(bh, sbh + (size_t)(wn * 32 + j * 16) * PAD + ks * 16, PAD);
                #pragma unroll
                for (int i = 0; i < 4; i++) wmma::mma_sync(acc[i][j], a[i], bh, acc[i][j]);
                if (use_lo) {
                    wmma::fragment<wmma::matrix_b, 16, 16, 16, __half, wmma::col_major> bl;
                    wmma::load_matrix_sync(bl, sbl + (size_t)(wn * 32 + j * 16) * PAD + ks * 16, PAD);
                    #pragma unroll
                    for (int i = 0; i < 4; i++) wmma::mma_sync(acc[i][j], a[i], bl, acc[i][j]);
                }
            }
        }
        __syncthreads();
    }

    // epilogue
    float* stg = (float*)smraw + (size_t)wid * (64 * 32);
    #pragma unroll
    for (int i = 0; i < 4; i++)
        #pragma unroll
        for (int j = 0; j < 2; j++)
            wmma::store_matrix_sync(stg + i * 16 * 32 + j * 16, acc[i][j], 32, wmma::mem_row_major);
    __syncwarp();

    const int nw0 = n0 + wn * 32;
    #pragma unroll
    for (int l = 0; l < 16; l++) {
        int idx = lane + l * 32;
        int r   = idx >> 3;
        int c4  = (idx & 7) * 4;
        float4 v = *(const float4*)(stg + r * 32 + c4);
        float4 bv = *(const float4*)&bias[nw0 + c4];
        v.x += bv.x; v.y += bv.y; v.z += bv.z; v.w += bv.w;
        const int m = m0 + wm * 64 + r;
        if (MODE == 0) {
            const int b = m >> 11, sq = m & 2047;
            const int hd = nw0 >> 6, d0 = (nw0 & 63) + c4;
            const size_t o = ((((size_t)b * HH + hd) * SS) + sq) * DD + d0;
            const float sc = (z == 0) ? 0.125f : 1.0f;
            __half* dst = (z == 0) ? g_qh : (z == 1) ? g_kh : g_vh;
            *(__half2*)(dst + o)     = __floats2half2_rn(v.x * sc, v.y * sc);
            *(__half2*)(dst + o + 2) = __floats2half2_rn(v.z * sc, v.w * sc);
        } else {
            *(float4*)&outp[(size_t)m * 1024 + nw0 + c4] = v;
        }
    }
}

// ---------------- WMMA fp16 flash attention, in-register softmax ----------------
#define KT_LD 72
#define KT_E  (64 * KT_LD)
#define F_LD  68
#define ATTN_SMEM (6 * KT_E * 2 + 64 * F_LD * 4)   // 72704

__global__ __launch_bounds__(128)
void attn3()
{
    extern __shared__ char smraw[];
    __half* sQ = (__half*)smraw;
    __half* sK = sQ + KT_E;              // [2][KT_E]
    __half* sV = sK + 2 * KT_E;          // [2][KT_E]
    __half* sP = sV + 2 * KT_E;
    float* sS = (float*)(sP + KT_E);     // discovery + epilogue staging only

    const int tid  = threadIdx.x;
    const int warp = tid >> 5;
    const int qt = blockIdx.x, hh = blockIdx.y, bb = blockIdx.z;
    const int row  = tid >> 1;
    const int half = tid & 1;
    const size_t hbase = (((size_t)bb * HH + hh) * SS) * DD;

    // Q group
    {
        const __half* qtile = g_qh + hbase + (size_t)qt * 64 * DD;
        #pragma unroll
        for (int i = 0; i < 4; i++) {
            int u = i * 128 + tid;
            int r = u >> 3, sg = u & 7;
            CP_ASYNC16(smem_u32(sQ + r * KT_LD + sg * 8), qtile + r * 64 + sg * 8);
        }
        CP_ASYNC_COMMIT();
    }
    // kt=0 K/V into buffer 0
    {
        const __half* kt0 = g_kh + hbase;
        const __half* vt0 = g_vh + hbase;
        #pragma unroll
        for (int i = 0; i < 4; i++) {
            int u = i * 128 + tid;
            int r = u >> 3, sg = u & 7;
            int so = r * KT_LD + sg * 8, go = r * 64 + sg * 8;
            CP_ASYNC16(smem_u32(sK + so), kt0 + go);
            CP_ASYNC16(smem_u32(sV + so), vt0 + go);
        }
        CP_ASYNC_COMMIT();
    }

    // layout discovery: acc element -> (row, col) via value = row*16 + col
    for (int i = tid; i < 256; i += 128)
        sS[(i >> 4) * F_LD + (i & 15)] = (float)i;
    __syncthreads();
    int rowidx[8], colidx[8];
    {
        wmma::fragment<wmma::accumulator, 16, 16, 16, float> rfrag;
        wmma::load_matrix_sync(rfrag, sS, F_LD, wmma::mem_row_major);
        #pragma unroll
        for (int i = 0; i < 8; i++) {
            int v = (int)rfrag.x[i];
            rowidx[i] = v >> 4;
            colidx[i] = v & 15;
        }
    }
    int rlo = rowidx[0];
    #pragma unroll
    for (int i = 1; i < 8; i++) rlo = min(rlo, rowidx[i]);
    bool paired = true;
    #pragma unroll
    for (int p4 = 0; p4 < 4; p4++)
        paired = paired && (rowidx[2*p4+1] == rowidx[2*p4]) && (colidx[2*p4+1] == colidx[2*p4] + 1);

    CP_ASYNC_WAIT1();   // Q done
    __syncthreads();    // discovery loads done; Q visible

    wmma::fragment<wmma::matrix_a, 16, 16, 16, __half, wmma::row_major> aQ[4];
    #pragma unroll
    for (int kk = 0; kk < 4; kk++)
        wmma::load_matrix_sync(aQ[kk], sQ + (size_t)(warp * 16) * KT_LD + kk * 16, KT_LD);

    wmma::fragment<wmma::accumulator, 16, 16, 16, float> accO[4];
    #pragma unroll
    for (int j = 0; j < 4; j++) wmma::fill_fragment(accO[j], 0.0f);

    float m_lo = -INFINITY, m_hi = -INFINITY;
    float l_lo = 0.0f, l_hi = 0.0f;

    for (int kt = 0; kt <= qt; kt++) {
        __syncthreads();
        if (kt < qt) {
            const __half* kn = g_kh + hbase + (size_t)(kt + 1) * 64 * DD;
            const __half* vn = g_vh + hbase + (size_t)(kt + 1) * 64 * DD;
            __half* dK = sK + ((kt + 1) & 1) * KT_E;
            __half* dV = sV + ((kt + 1) & 1) * KT_E;
            #pragma unroll
            for (int i = 0; i < 4; i++) {
                int u = i * 128 + tid;
                int r = u >> 3, sg = u & 7;
                int so = r * KT_LD + sg * 8, go = r * 64 + sg * 8;
                CP_ASYNC16(smem_u32(dK + so), kn + go);
                CP_ASYNC16(smem_u32(dV + so), vn + go);
            }
            CP_ASYNC_COMMIT();
            CP_ASYNC_WAIT1();
        } else {
            CP_ASYNC_WAIT0();
        }
        __syncthreads();

        const __half* cK = sK + (kt & 1) * KT_E;
        const __half* cV = sV + (kt & 1) * KT_E;

        // ---- scores into registers ----
        wmma::fragment<wmma::accumulator, 16, 16, 16, float> accS[4];
        #pragma unroll
        for (int j = 0; j < 4; j++) wmma::fill_fragment(accS[j], 0.0f);
        #pragma unroll
        for (int kk = 0; kk < 4; kk++) {
            #pragma unroll
            for (int j = 0; j < 4; j++) {
                wmma::fragment<wmma::matrix_b, 16, 16, 16, __half, wmma::col_major> bK;
                wmma::load_matrix_sync(bK, cK + (size_t)(j * 16) * KT_LD + kk * 16, KT_LD);
                wmma::mma_sync(accS[j], aQ[kk], bK, accS[j]);
            }
        }

        // ---- in-register softmax ----
        const bool diag = (kt == qt);
        float mx_lo = -INFINITY, mx_hi = -INFINITY;
        #pragma unroll
        for (int j = 0; j < 4; j++)
            #pragma unroll
            for (int i = 0; i < 8; i++) {
                float v = accS[j].x[i];
                if (diag && (j * 16 + colidx[i] > warp * 16 + rowidx[i])) v = -INFINITY;
                accS[j].x[i] = v;
                if (rowidx[i] == rlo) mx_lo = fmaxf(mx_lo, v); else mx_hi = fmaxf(mx_hi, v);
            }
        mx_lo = fmaxf(mx_lo, __shfl_xor_sync(0xffffffffu, mx_lo, 1));
        mx_lo = fmaxf(mx_lo, __shfl_xor_sync(0xffffffffu, mx_lo, 2));
        mx_hi = fmaxf(mx_hi, __shfl_xor_sync(0xffffffffu, mx_hi, 1));
        mx_hi = fmaxf(mx_hi, __shfl_xor_sync(0xffffffffu, mx_hi, 2));
        const float mn_lo = fmaxf(m_lo, mx_lo);
        const float mn_hi = fmaxf(m_hi, mx_hi);
        const float al_lo = __expf(m_lo - mn_lo);
        const float al_hi = __expf(m_hi - mn_hi);
        float ps_lo = 0.0f, ps_hi = 0.0f;
        #pragma unroll
        for (int j = 0; j < 4; j++)
            #pragma unroll
            for (int i = 0; i < 8; i++) {
                const bool lo = (rowidx[i] == rlo);
                float p = __expf(accS[j].x[i] - (lo ? mn_lo : mn_hi));
                accS[j].x[i] = p;
                if (lo) ps_lo += p; else ps_hi += p;
            }
        ps_lo += __shfl_xor_sync(0xffffffffu, ps_lo, 1);
        ps_lo += __shfl_xor_sync(0xffffffffu, ps_lo, 2);
        ps_hi += __shfl_xor_sync(0xffffffffu, ps_hi, 1);
        ps_hi += __shfl_xor_sync(0xffffffffu, ps_hi, 2);
        l_lo = l_lo * al_lo + ps_lo;  m_lo = mn_lo;
        l_hi = l_hi * al_hi + ps_hi;  m_hi = mn_hi;

        // ---- store P (warp-private rows) ----
        if (paired) {
            #pragma unroll
            for (int j = 0; j < 4; j++)
                #pragma unroll
                for (int p4 = 0; p4 < 4; p4++) {
                    const int i0 = 2 * p4;
                    __half2 hv = __floats2half2_rn(accS[j].x[i0], accS[j].x[i0 + 1]);
                    *(__half2*)(sP + (size_t)(warp * 16 + rowidx[i0]) * KT_LD + j * 16 + colidx[i0]) = hv;
                }
        } else {
            #pragma unroll
            for (int j = 0; j < 4; j++)
                #pragma unroll
                for (int i = 0; i < 8; i++)
                    sP[(size_t)(warp * 16 + rowidx[i]) * KT_LD + j * 16 + colidx[i]] = __float2half_rn(accS[j].x[i]);
        }
        __syncwarp();

        // ---- PV with in-register rescale ----
        #pragma unroll
        for (int j = 0; j < 4; j++)
            #pragma unroll
            for (int i = 0; i < 8; i++)
                accO[j].x[i] *= (rowidx[i] == rlo) ? al_lo : al_hi;
        #pragma unroll
        for (int kk = 0; kk < 4; kk++) {
            wmma::fragment<wmma::matrix_a, 16, 16, 16, __half, wmma::row_major> aP;
            wmma::load_matrix_sync(aP, sP + (size_t)(warp * 16) * KT_LD + kk * 16, KT_LD);
            #pragma unroll
            for (int j = 0; j < 4; j++) {
                wmma::fragment<wmma::matrix_b, 16, 16, 16, __half, wmma::row_major> bV;
                wmma::load_matrix_sync(bV, cV + (size_t)(kk * 16) * KT_LD + j * 16, KT_LD);
                wmma::mma_sync(accO[j], aP, bV, accO[j]);
            }
        }
    }

    // epilogue: normalize in-register, stage via sS (warp-private), write fp16
    {
        const float inv_lo = 1.0f / l_lo;
        const float inv_hi = 1.0f / l_hi;
        #pragma unroll
        for (int j = 0; j < 4; j++)
            #pragma unroll
            for (int i = 0; i < 8; i++)
                accO[j].x[i] *= (rowidx[i] == rlo) ? inv_lo : inv_hi;
        #pragma unroll
        for (int j = 0; j < 4; j++)
            wmma::store_matrix_sync(sS + (size_t)(warp * 16) * F_LD + j * 16, accO[j], F_LD, wmma::mem_row_major);
    }
    __syncwarp();
    {
        const float* orow = sS + (size_t)row * F_LD + half * 32;
        const size_t go = ((size_t)bb * SS + (size_t)qt * 64 + row) * EE + hh * DD + half * 32;
        #pragma unroll
        for (int c8 = 0; c8 < 8; c8++) {
            float4 v = *(const float4*)(orow + 4 * c8);
            *(__half2*)(g_xh + go + 4*c8)     = __floats2half2_rn(v.x, v.y);
            *(__half2*)(g_xh + go + 4*c8 + 2) = __floats2half2_rn(v.z, v.w);
        }
    }
}

// ---------------------------------------------------------------------------
extern "C" void kernel_launch(void* const* d_in, const int* in_sizes, int n_in,
                              void* d_out, int out_size)
{
    const float* x  = (const float*)d_in[0];
    const float* Wq = (const float*)d_in[1];
    const float* bq = (const float*)d_in[2];
    const float* Wk = (const float*)d_in[3];
    const float* bk = (const float*)d_in[4];
    const float* Wv = (const float*)d_in[5];
    const float* bv = (const float*)d_in[6];
    const float* Wo = (const float*)d_in[7];
    const float* bo = (const float*)d_in[8];
    float* out = (float*)d_out;

    cudaFuncSetAttribute(wgemm<0>, cudaFuncAttributeMaxDynamicSharedMemorySize, GEMM_SMEM);
    cudaFuncSetAttribute(wgemm<1>, cudaFuncAttributeMaxDynamicSharedMemorySize, GEMM_SMEM);
    cudaFuncSetAttribute(attn3,    cudaFuncAttributeMaxDynamicSharedMemorySize, ATTN_SMEM);

    conv_x<<<MM * EE / 2048, 256>>>(x);
    conv_w4<<<dim3(32, 32, 4), 256>>>(Wq, Wk, Wv, Wo);
    wgemm<0><<<dim3(EE / 128, MM / 128, 3), 256, GEMM_SMEM>>>(bq, bk, bv, nullptr);
    attn3<<<dim3(SS / 64, HH, BB), 128, ATTN_SMEM>>>();
    wgemm<1><<<dim3(EE / 128, MM / 128, 1), 256, GEMM_SMEM>>>(bo, nullptr, nullptr, out);
}

// round 10
// speedup vs baseline: 2.3211x; 1.0010x over previous
#include <cuda_runtime.h>
#include <cuda_fp16.h>
#include <mma.h>
#include <cstdint>
#include <math.h>

using namespace nvcuda;

#define BB 4
#define SS 2048
#define EE 1024
#define HH 16
#define DD 64
#define MM (BB*SS)   // 8192

// ---------------- device scratch (allocation-free contract) ----------------
__device__ __align__(16) __half g_xh[(size_t)MM*EE];        // A operand fp16 [M,K]; attn writes O here
__device__ __align__(16) __half g_wth[4*(size_t)EE*EE];     // W^T fp16 [slot][N,K]
__device__ __align__(16) __half g_qh[(size_t)BB*HH*SS*DD];  // Q fp16 (pre-scaled 1/8)
__device__ __align__(16) __half g_kh[(size_t)BB*HH*SS*DD];  // K fp16
__device__ __align__(16) __half g_vh[(size_t)BB*HH*SS*DD];  // V fp16

// ---------------- helpers ----------------
__device__ __forceinline__ uint32_t smem_u32(const void* p) {
    uint32_t a;
    asm("{ .reg .u64 t; cvta.to.shared.u64 t, %1; cvt.u32.u64 %0, t; }" : "=r"(a) : "l"(p));
    return a;
}
#define CP_ASYNC16(sa, g)  asm volatile("cp.async.cg.shared.global [%0], [%1], 16;" :: "r"(sa), "l"(g) : "memory")
#define CP_ASYNC_COMMIT()  asm volatile("cp.async.commit_group;" ::: "memory")
#define CP_ASYNC_WAIT0()   asm volatile("cp.async.wait_group 0;" ::: "memory")
#define CP_ASYNC_WAIT1()   asm volatile("cp.async.wait_group 1;" ::: "memory")
#define CP_ASYNC_WAIT2()   asm volatile("cp.async.wait_group 2;" ::: "memory")

// ---------------- converters ----------------
__global__ __launch_bounds__(256) void conv_x(const float* __restrict__ in) {
    size_t i = ((size_t)blockIdx.x * 256 + threadIdx.x) * 8;
    float4 a = *(const float4*)(in + i);
    float4 b = *(const float4*)(in + i + 4);
    __half2 o[4];
    o[0] = __floats2half2_rn(a.x, a.y);
    o[1] = __floats2half2_rn(a.z, a.w);
    o[2] = __floats2half2_rn(b.x, b.y);
    o[3] = __floats2half2_rn(b.z, b.w);
    *(uint4*)(g_xh + i) = *(uint4*)o;
}

// all four weights -> single fp16 W^T
__global__ __launch_bounds__(256) void conv_w4(const float* __restrict__ W0,
                                               const float* __restrict__ W1,
                                               const float* __restrict__ W2,
                                               const float* __restrict__ W3) {
    __shared__ float t[32][33];
    const int tx = threadIdx.x & 31, ty = threadIdx.x >> 5;
    const int n0 = blockIdx.x * 32, k0 = blockIdx.y * 32;
    const int z = blockIdx.z;
    const float* W = (z == 0) ? W0 : (z == 1) ? W1 : (z == 2) ? W2 : W3;
    __half* wh = g_wth + (size_t)z * EE * EE;
    #pragma unroll
    for (int j = 0; j < 4; j++)
        t[ty + 8*j][tx] = W[(size_t)(k0 + ty + 8*j) * 1024 + n0 + tx];
    __syncthreads();
    #pragma unroll
    for (int j = 0; j < 4; j++) {
        float v = t[tx][ty + 8*j];
        wh[(size_t)(n0 + ty + 8*j) * 1024 + k0 + tx] = __float2half_rn(v);
    }
}

// ---------------- WMMA fp16 GEMM, 3-stage cp.async pipeline ----------------
#define PAD 40
#define TILE_B   (128 * PAD * 2)
#define TILE_E   (128 * PAD)
#define STAGE_B  (2 * TILE_B)       // A, B
#define STAGE_E  (2 * TILE_E)
#define GEMM_SMEM 65536             // max(3*STAGE_B=61440, epilogue 8*64*32*4=65536)

__device__ __forceinline__ void stage_load(uint32_t sb,
    const __half* A, const __half* Bh, int k0, int tid)
{
    #pragma unroll
    for (int t = 0; t < 2; t++) {
        int u   = tid + t * 256;
        int row = u >> 2;
        int seg = u & 3;
        uint32_t off = (uint32_t)row * (PAD * 2) + seg * 16;
        size_t g = (size_t)row * 1024 + k0 + seg * 8;
        CP_ASYNC16(sb + off,          A  + g);
        CP_ASYNC16(sb + TILE_B + off, Bh + g);
    }
}

// MODE 0: fused QKV (z = 0/1/2); MODE 1: O projection (slot 3, fp32 out)
template<int MODE>
__global__ __launch_bounds__(256)
void wgemm(const float* __restrict__ bias0, const float* __restrict__ bias1,
           const float* __restrict__ bias2, float* __restrict__ outp)
{
    extern __shared__ char smraw[];
    __half* s = (__half*)smraw;
    const uint32_t sbase = smem_u32(smraw);

    const int tid  = threadIdx.x;
    const int wid  = tid >> 5, lane = tid & 31;
    const int wm   = wid >> 2, wn = wid & 3;
    const int m0   = blockIdx.y * 128;
    const int n0   = blockIdx.x * 128;
    const int z    = (MODE == 0) ? blockIdx.z : 3;
    const float* bias = (MODE == 1) ? bias0 : (z == 0 ? bias0 : z == 1 ? bias1 : bias2);

    const __half* A  = g_xh + (size_t)m0 * 1024;
    const __half* Bh = g_wth + (size_t)z * EE * EE + (size_t)n0 * 1024;

    wmma::fragment<wmma::accumulator, 16, 16, 16, float> acc[4][2];
    #pragma unroll
    for (int i = 0; i < 4; i++)
        #pragma unroll
        for (int j = 0; j < 2; j++) wmma::fill_fragment(acc[i][j], 0.0f);

    stage_load(sbase,               A, Bh, 0,  tid); CP_ASYNC_COMMIT();
    stage_load(sbase + STAGE_B,     A, Bh, 32, tid); CP_ASYNC_COMMIT();

    for (int kc = 0; kc < 32; kc++) {
        if (kc + 2 < 32) {
            stage_load(sbase + ((kc + 2) % 3) * STAGE_B, A, Bh, (kc + 2) * 32, tid);
            CP_ASYNC_COMMIT();
            CP_ASYNC_WAIT2();
        } else if (kc + 2 == 32) {
            CP_ASYNC_WAIT1();
        } else {
            CP_ASYNC_WAIT0();
        }
        __syncthreads();

        const __half* st  = s + (kc % 3) * STAGE_E;
        const __half* sa  = st;
        const __half* sbh = st + TILE_E;

        #pragma unroll
        for (int ks = 0; ks < 2; ks++) {
            wmma::fragment<wmma::matrix_a, 16, 16, 16, __half, wmma::row_major> a[4];
            #pragma unroll
            for (int i = 0; i < 4; i++)
                wmma::load_matrix_sync(a[i], sa + (size_t)(wm * 64 + i * 16) * PAD + ks * 16, PAD);
            #pragma unroll
            for (int j = 0; j < 2; j++) {
                wmma::fragment<wmma::matrix_b, 16, 16, 16, __half, wmma::col_major> bh;
                wmma::load_matrix_sync(bh, sbh + (size_t)(wn * 32 + j * 16) * PAD + ks * 16, PAD);
                #pragma unroll
                for (int i = 0; i < 4; i++) wmma::mma_sync(acc[i][j], a[i], bh, acc[i][j]);
            }
        }
        __syncthreads();
    }

    // epilogue
    float* stg = (float*)smraw + (size_t)wid * (64 * 32);
    #pragma unroll
    for (int i = 0; i < 4; i++)
        #pragma unroll
        for (int j = 0; j < 2; j++)
            wmma::store_matrix_sync(stg + i * 16 * 32 + j * 16, acc[i][j], 32, wmma::mem_row_major);
    __syncwarp();

    const int nw0 = n0 + wn * 32;
    #pragma unroll
    for (int l = 0; l < 16; l++) {
        int idx = lane + l * 32;
        int r   = idx >> 3;
        int c4  = (idx & 7) * 4;
        float4 v = *(const float4*)(stg + r * 32 + c4);
        float4 bv = *(const float4*)&bias[nw0 + c4];
        v.x += bv.x; v.y += bv.y; v.z += bv.z; v.w += bv.w;
        const int m = m0 + wm * 64 + r;
        if (MODE == 0) {
            const int b = m >> 11, sq = m & 2047;
            const int hd = nw0 >> 6, d0 = (nw0 & 63) + c4;
            const size_t o = ((((size_t)b * HH + hd) * SS) + sq) * DD + d0;
            const float sc = (z == 0) ? 0.125f : 1.0f;
            __half* dst = (z == 0) ? g_qh : (z == 1) ? g_kh : g_vh;
            *(__half2*)(dst + o)     = __floats2half2_rn(v.x * sc, v.y * sc);
            *(__half2*)(dst + o + 2) = __floats2half2_rn(v.z * sc, v.w * sc);
        } else {
            *(float4*)&outp[(size_t)m * 1024 + nw0 + c4] = v;
        }
    }
}

// ---------------- WMMA fp16 flash attention, in-register softmax ----------------
#define KT_LD 72
#define KT_E  (64 * KT_LD)
#define F_LD  68
#define ATTN_SMEM (6 * KT_E * 2 + 64 * F_LD * 4)   // 72704

__global__ __launch_bounds__(128)
void attn3()
{
    extern __shared__ char smraw[];
    __half* sQ = (__half*)smraw;
    __half* sK = sQ + KT_E;              // [2][KT_E]
    __half* sV = sK + 2 * KT_E;          // [2][KT_E]
    __half* sP = sV + 2 * KT_E;
    float* sS = (float*)(sP + KT_E);     // discovery + epilogue staging only

    const int tid  = threadIdx.x;
    const int warp = tid >> 5;
    const int qt = blockIdx.x, hh = blockIdx.y, bb = blockIdx.z;
    const int row  = tid >> 1;
    const int half = tid & 1;
    const size_t hbase = (((size_t)bb * HH + hh) * SS) * DD;

    // Q group
    {
        const __half* qtile = g_qh + hbase + (size_t)qt * 64 * DD;
        #pragma unroll
        for (int i = 0; i < 4; i++) {
            int u = i * 128 + tid;
            int r = u >> 3, sg = u & 7;
            CP_ASYNC16(smem_u32(sQ + r * KT_LD + sg * 8), qtile + r * 64 + sg * 8);
        }
        CP_ASYNC_COMMIT();
    }
    // kt=0 K/V into buffer 0
    {
        const __half* kt0 = g_kh + hbase;
        const __half* vt0 = g_vh + hbase;
        #pragma unroll
        for (int i = 0; i < 4; i++) {
            int u = i * 128 + tid;
            int r = u >> 3, sg = u & 7;
            int so = r * KT_LD + sg * 8, go = r * 64 + sg * 8;
            CP_ASYNC16(smem_u32(sK + so), kt0 + go);
            CP_ASYNC16(smem_u32(sV + so), vt0 + go);
        }
        CP_ASYNC_COMMIT();
    }

    // layout discovery: acc element -> (row, col) via value = row*16 + col
    for (int i = tid; i < 256; i += 128)
        sS[(i >> 4) * F_LD + (i & 15)] = (float)i;
    __syncthreads();
    int rowidx[8], colidx[8];
    {
        wmma::fragment<wmma::accumulator, 16, 16, 16, float> rfrag;
        wmma::load_matrix_sync(rfrag, sS, F_LD, wmma::mem_row_major);
        #pragma unroll
        for (int i = 0; i < 8; i++) {
            int v = (int)rfrag.x[i];
            rowidx[i] = v >> 4;
            colidx[i] = v & 15;
        }
    }
    int rlo = rowidx[0];
    #pragma unroll
    for (int i = 1; i < 8; i++) rlo = min(rlo, rowidx[i]);
    bool isLo[8];
    #pragma unroll
    for (int i = 0; i < 8; i++) isLo[i] = (rowidx[i] == rlo);
    bool paired = true;
    #pragma unroll
    for (int p4 = 0; p4 < 4; p4++)
        paired = paired && (rowidx[2*p4+1] == rowidx[2*p4]) && (colidx[2*p4+1] == colidx[2*p4] + 1);

    CP_ASYNC_WAIT1();   // Q done
    __syncthreads();    // discovery loads done; Q visible

    wmma::fragment<wmma::matrix_a, 16, 16, 16, __half, wmma::row_major> aQ[4];
    #pragma unroll
    for (int kk = 0; kk < 4; kk++)
        wmma::load_matrix_sync(aQ[kk], sQ + (size_t)(warp * 16) * KT_LD + kk * 16, KT_LD);

    wmma::fragment<wmma::accumulator, 16, 16, 16, float> accO[4];
    #pragma unroll
    for (int j = 0; j < 4; j++) wmma::fill_fragment(accO[j], 0.0f);

    float m_lo = -INFINITY, m_hi = -INFINITY;
    float l_lo = 0.0f, l_hi = 0.0f;

    #pragma unroll 2
    for (int kt = 0; kt <= qt; kt++) {
        __syncthreads();
        if (kt < qt) {
            const __half* kn = g_kh + hbase + (size_t)(kt + 1) * 64 * DD;
            const __half* vn = g_vh + hbase + (size_t)(kt + 1) * 64 * DD;
            __half* dK = sK + ((kt + 1) & 1) * KT_E;
            __half* dV = sV + ((kt + 1) & 1) * KT_E;
            #pragma unroll
            for (int i = 0; i < 4; i++) {
                int u = i * 128 + tid;
                int r = u >> 3, sg = u & 7;
                int so = r * KT_LD + sg * 8, go = r * 64 + sg * 8;
                CP_ASYNC16(smem_u32(dK + so), kn + go);
                CP_ASYNC16(smem_u32(dV + so), vn + go);
            }
            CP_ASYNC_COMMIT();
            CP_ASYNC_WAIT1();
        } else {
            CP_ASYNC_WAIT0();
        }
        __syncthreads();

        const __half* cK = sK + (kt & 1) * KT_E;
        const __half* cV = sV + (kt & 1) * KT_E;

        // ---- scores into registers ----
        wmma::fragment<wmma::accumulator, 16, 16, 16, float> accS[4];
        #pragma unroll
        for (int j = 0; j < 4; j++) wmma::fill_fragment(accS[j], 0.0f);
        #pragma unroll
        for (int kk = 0; kk < 4; kk++) {
            #pragma unroll
            for (int j = 0; j < 4; j++) {
                wmma::fragment<wmma::matrix_b, 16, 16, 16, __half, wmma::col_major> bK;
                wmma::load_matrix_sync(bK, cK + (size_t)(j * 16) * KT_LD + kk * 16, KT_LD);
                wmma::mma_sync(accS[j], aQ[kk], bK, accS[j]);
            }
        }

        // ---- in-register softmax ----
        const bool diag = (kt == qt);
        if (diag) {
            #pragma unroll
            for (int j = 0; j < 4; j++)
                #pragma unroll
                for (int i = 0; i < 8; i++)
                    if (j * 16 + colidx[i] > warp * 16 + rowidx[i]) accS[j].x[i] = -INFINITY;
        }
        float mx_lo = -INFINITY, mx_hi = -INFINITY;
        #pragma unroll
        for (int j = 0; j < 4; j++)
            #pragma unroll
            for (int i = 0; i < 8; i++) {
                float v = accS[j].x[i];
                if (isLo[i]) mx_lo = fmaxf(mx_lo, v); else mx_hi = fmaxf(mx_hi, v);
            }
        mx_lo = fmaxf(mx_lo, __shfl_xor_sync(0xffffffffu, mx_lo, 1));
        mx_lo = fmaxf(mx_lo, __shfl_xor_sync(0xffffffffu, mx_lo, 2));
        mx_hi = fmaxf(mx_hi, __shfl_xor_sync(0xffffffffu, mx_hi, 1));
        mx_hi = fmaxf(mx_hi, __shfl_xor_sync(0xffffffffu, mx_hi, 2));
        const float mn_lo = fmaxf(m_lo, mx_lo);
        const float mn_hi = fmaxf(m_hi, mx_hi);
        const float al_lo = __expf(m_lo - mn_lo);
        const float al_hi = __expf(m_hi - mn_hi);
        float ps_lo = 0.0f, ps_hi = 0.0f;
        #pragma unroll
        for (int j = 0; j < 4; j++)
            #pragma unroll
            for (int i = 0; i < 8; i++) {
                float p = __expf(accS[j].x[i] - (isLo[i] ? mn_lo : mn_hi));
                accS[j].x[i] = p;
                if (isLo[i]) ps_lo += p; else ps_hi += p;
            }
        ps_lo += __shfl_xor_sync(0xffffffffu, ps_lo, 1);
        ps_lo += __shfl_xor_sync(0xffffffffu, ps_lo, 2);
        ps_hi += __shfl_xor_sync(0xffffffffu, ps_hi, 1);
        ps_hi += __shfl_xor_sync(0xffffffffu, ps_hi, 2);
        l_lo = l_lo * al_lo + ps_lo;  m_lo = mn_lo;
        l_hi = l_hi * al_hi + ps_hi;  m_hi = mn_hi;

        // ---- store P (warp-private rows) ----
        if (paired) {
            #pragma unroll
            for (int j = 0; j < 4; j++)
                #pragma unroll
                for (int p4 = 0; p4 < 4; p4++) {
                    const int i0 = 2 * p4;
                    __half2 hv = __floats2half2_rn(accS[j].x[i0], accS[j].x[i0 + 1]);
                    *(__half2*)(sP + (size_t)(warp * 16 + rowidx[i0]) * KT_LD + j * 16 + colidx[i0]) = hv;
                }
        } else {
            #pragma unroll
            for (int j = 0; j < 4; j++)
                #pragma unroll
                for (int i = 0; i < 8; i++)
                    sP[(size_t)(warp * 16 + rowidx[i]) * KT_LD + j * 16 + colidx[i]] = __float2half_rn(accS[j].x[i]);
        }
        __syncwarp();

        // ---- PV with in-register rescale ----
        #pragma unroll
        for (int j = 0; j < 4; j++)
            #pragma unroll
            for (int i = 0; i < 8; i++)
                accO[j].x[i] *= (isLo[i]) ? al_lo : al_hi;
        #pragma unroll
        for (int kk = 0; kk < 4; kk++) {
            wmma::fragment<wmma::matrix_a, 16, 16, 16, __half, wmma::row_major> aP;
            wmma::load_matrix_sync(aP, sP + (size_t)(warp * 16) * KT_LD + kk * 16, KT_LD);
            #pragma unroll
            for (int j = 0; j < 4; j++) {
                wmma::fragment<wmma::matrix_b, 16, 16, 16, __half, wmma::row_major> bV;
                wmma::load_matrix_sync(bV, cV + (size_t)(kk * 16) * KT_LD + j * 16, KT_LD);
                wmma::mma_sync(accO[j], aP, bV, accO[j]);
            }
        }
    }

    // epilogue: normalize in-register, stage via sS (warp-private), write fp16
    {
        const float inv_lo = 1.0f / l_lo;
        const float inv_hi = 1.0f / l_hi;
        #pragma unroll
        for (int j = 0; j < 4; j++)
            #pragma unroll
            for (int i = 0; i < 8; i++)
                accO[j].x[i] *= (isLo[i]) ? inv_lo : inv_hi;
        #pragma unroll
        for (int j = 0; j < 4; j++)
            wmma::store_matrix_sync(sS + (size_t)(warp * 16) * F_LD + j * 16, accO[j], F_LD, wmma::mem_row_major);
    }
    __syncwarp();
    {
        const float* orow = sS + (size_t)row * F_LD + half * 32;
        const size_t go = ((size_t)bb * SS + (size_t)qt * 64 + row) * EE + hh * DD + half * 32;
        #pragma unroll
        for (int c8 = 0; c8 < 8; c8++) {
            float4 v = *(const float4*)(orow + 4 * c8);
            *(__half2*)(g_xh + go + 4*c8)     = __floats2half2_rn(v.x, v.y);
            *(__half2*)(g_xh + go + 4*c8 + 2) = __floats2half2_rn(v.z, v.w);
        }
    }
}

// ---------------------------------------------------------------------------
extern "C" void kernel_launch(void* const* d_in, const int* in_sizes, int n_in,
                              void* d_out, int out_size)
{
    const float* x  = (const float*)d_in[0];
    const float* Wq = (const float*)d_in[1];
    const float* bq = (const float*)d_in[2];
    const float* Wk = (const float*)d_in[3];
    const float* bk = (const float*)d_in[4];
    const float* Wv = (const float*)d_in[5];
    const float* bv = (const float*)d_in[6];
    const float* Wo = (const float*)d_in[7];
    const float* bo = (const float*)d_in[8];
    float* out = (float*)d_out;

    cudaFuncSetAttribute(wgemm<0>, cudaFuncAttributeMaxDynamicSharedMemorySize, GEMM_SMEM);
    cudaFuncSetAttribute(wgemm<1>, cudaFuncAttributeMaxDynamicSharedMemorySize, GEMM_SMEM);
    cudaFuncSetAttribute(attn3,    cudaFuncAttributeMaxDynamicSharedMemorySize, ATTN_SMEM);

    conv_x<<<MM * EE / 2048, 256>>>(x);
    conv_w4<<<dim3(32, 32, 4), 256>>>(Wq, Wk, Wv, Wo);
    wgemm<0><<<dim3(EE / 128, MM / 128, 3), 256, GEMM_SMEM>>>(bq, bk, bv, nullptr);
    attn3<<<dim3(SS / 64, HH, BB), 128, ATTN_SMEM>>>();
    wgemm<1><<<dim3(EE / 128, MM / 128, 1), 256, GEMM_SMEM>>>(bo, nullptr, nullptr, out);
}

// round 11
// speedup vs baseline: 2.6074x; 1.1233x over previous
#include <cuda_runtime.h>
#include <cuda_fp16.h>
#include <mma.h>
#include <cstdint>
#include <math.h>

using namespace nvcuda;

#define BB 4
#define SS 2048
#define EE 1024
#define HH 16
#define DD 64
#define MM (BB*SS)   // 8192

// ---------------- device scratch (allocation-free contract) ----------------
__device__ __align__(16) __half g_xh[(size_t)MM*EE];        // A operand fp16 [M,K]; attn writes O here
__device__ __align__(16) __half g_wth[4*(size_t)EE*EE];     // W^T fp16 [slot][N,K]
__device__ __align__(16) __half g_qh[(size_t)BB*HH*SS*DD];  // Q fp16 (pre-scaled 1/8)
__device__ __align__(16) __half g_kh[(size_t)BB*HH*SS*DD];  // K fp16
__device__ __align__(16) __half g_vh[(size_t)BB*HH*SS*DD];  // V fp16

// ---------------- helpers ----------------
__device__ __forceinline__ uint32_t smem_u32(const void* p) {
    uint32_t a;
    asm("{ .reg .u64 t; cvta.to.shared.u64 t, %1; cvt.u32.u64 %0, t; }" : "=r"(a) : "l"(p));
    return a;
}
#define CP_ASYNC16(sa, g)  asm volatile("cp.async.cg.shared.global [%0], [%1], 16;" :: "r"(sa), "l"(g) : "memory")
#define CP_ASYNC_COMMIT()  asm volatile("cp.async.commit_group;" ::: "memory")
#define CP_ASYNC_WAIT0()   asm volatile("cp.async.wait_group 0;" ::: "memory")
#define CP_ASYNC_WAIT1()   asm volatile("cp.async.wait_group 1;" ::: "memory")
#define CP_ASYNC_WAIT2()   asm volatile("cp.async.wait_group 2;" ::: "memory")

// ---------------- converters ----------------
__global__ __launch_bounds__(256) void conv_x(const float* __restrict__ in) {
    size_t i = ((size_t)blockIdx.x * 256 + threadIdx.x) * 8;
    float4 a = *(const float4*)(in + i);
    float4 b = *(const float4*)(in + i + 4);
    __half2 o[4];
    o[0] = __floats2half2_rn(a.x, a.y);
    o[1] = __floats2half2_rn(a.z, a.w);
    o[2] = __floats2half2_rn(b.x, b.y);
    o[3] = __floats2half2_rn(b.z, b.w);
    *(uint4*)(g_xh + i) = *(uint4*)o;
}

// all four weights -> single fp16 W^T
__global__ __launch_bounds__(256) void conv_w4(const float* __restrict__ W0,
                                               const float* __restrict__ W1,
                                               const float* __restrict__ W2,
                                               const float* __restrict__ W3) {
    __shared__ float t[32][33];
    const int tx = threadIdx.x & 31, ty = threadIdx.x >> 5;
    const int n0 = blockIdx.x * 32, k0 = blockIdx.y * 32;
    const int z = blockIdx.z;
    const float* W = (z == 0) ? W0 : (z == 1) ? W1 : (z == 2) ? W2 : W3;
    __half* wh = g_wth + (size_t)z * EE * EE;
    #pragma unroll
    for (int j = 0; j < 4; j++)
        t[ty + 8*j][tx] = W[(size_t)(k0 + ty + 8*j) * 1024 + n0 + tx];
    __syncthreads();
    #pragma unroll
    for (int j = 0; j < 4; j++) {
        float v = t[tx][ty + 8*j];
        wh[(size_t)(n0 + ty + 8*j) * 1024 + k0 + tx] = __float2half_rn(v);
    }
}

// ---------------- WMMA fp16 GEMM, 3-stage cp.async pipeline ----------------
#define PAD 40
#define TILE_B   (128 * PAD * 2)
#define TILE_E   (128 * PAD)
#define STAGE_B  (2 * TILE_B)       // A, B
#define STAGE_E  (2 * TILE_E)
#define GEMM_SMEM 65536             // max(3*STAGE_B=61440, epilogue 8*64*32*4=65536)

__device__ __forceinline__ void stage_load(uint32_t sb,
    const __half* A, const __half* Bh, int k0, int tid)
{
    #pragma unroll
    for (int t = 0; t < 2; t++) {
        int u   = tid + t * 256;
        int row = u >> 2;
        int seg = u & 3;
        uint32_t off = (uint32_t)row * (PAD * 2) + seg * 16;
        size_t g = (size_t)row * 1024 + k0 + seg * 8;
        CP_ASYNC16(sb + off,          A  + g);
        CP_ASYNC16(sb + TILE_B + off, Bh + g);
    }
}

// MODE 0: fused QKV (z = 0/1/2); MODE 1: O projection (slot 3, fp32 out)
template<int MODE>
__global__ __launch_bounds__(256)
void wgemm(const float* __restrict__ bias0, const float* __restrict__ bias1,
           const float* __restrict__ bias2, float* __restrict__ outp)
{
    extern __shared__ char smraw[];
    __half* s = (__half*)smraw;
    const uint32_t sbase = smem_u32(smraw);

    const int tid  = threadIdx.x;
    const int wid  = tid >> 5, lane = tid & 31;
    const int wm   = wid >> 2, wn = wid & 3;
    const int m0   = blockIdx.y * 128;
    const int n0   = blockIdx.x * 128;
    const int z    = (MODE == 0) ? blockIdx.z : 3;
    const float* bias = (MODE == 1) ? bias0 : (z == 0 ? bias0 : z == 1 ? bias1 : bias2);

    const __half* A  = g_xh + (size_t)m0 * 1024;
    const __half* Bh = g_wth + (size_t)z * EE * EE + (size_t)n0 * 1024;

    wmma::fragment<wmma::accumulator, 16, 16, 16, float> acc[4][2];
    #pragma unroll
    for (int i = 0; i < 4; i++)
        #pragma unroll
        for (int j = 0; j < 2; j++) wmma::fill_fragment(acc[i][j], 0.0f);

    stage_load(sbase,               A, Bh, 0,  tid); CP_ASYNC_COMMIT();
    stage_load(sbase + STAGE_B,     A, Bh, 32, tid); CP_ASYNC_COMMIT();

    for (int kc = 0; kc < 32; kc++) {
        if (kc + 2 < 32) {
            stage_load(sbase + ((kc + 2) % 3) * STAGE_B, A, Bh, (kc + 2) * 32, tid);
            CP_ASYNC_COMMIT();
            CP_ASYNC_WAIT2();
        } else if (kc + 2 == 32) {
            CP_ASYNC_WAIT1();
        } else {
            CP_ASYNC_WAIT0();
        }
        __syncthreads();

        const __half* st  = s + (kc % 3) * STAGE_E;
        const __half* sa  = st;
        const __half* sbh = st + TILE_E;

        #pragma unroll
        for (int ks = 0; ks < 2; ks++) {
            wmma::fragment<wmma::matrix_a, 16, 16, 16, __half, wmma::row_major> a[4];
            #pragma unroll
            for (int i = 0; i < 4; i++)
                wmma::load_matrix_sync(a[i], sa + (size_t)(wm * 64 + i * 16) * PAD + ks * 16, PAD);
            #pragma unroll
            for (int j = 0; j < 2; j++) {
                wmma::fragment<wmma::matrix_b, 16, 16, 16, __half, wmma::col_major> bh;
                wmma::load_matrix_sync(bh, sbh + (size_t)(wn * 32 + j * 16) * PAD + ks * 16, PAD);
                #pragma unroll
                for (int i = 0; i < 4; i++) wmma::mma_sync(acc[i][j], a[i], bh, acc[i][j]);
            }
        }
        __syncthreads();
    }

    // epilogue
    float* stg = (float*)smraw + (size_t)wid * (64 * 32);
    #pragma unroll
    for (int i = 0; i < 4; i++)
        #pragma unroll
        for (int j = 0; j < 2; j++)
            wmma::store_matrix_sync(stg + i * 16 * 32 + j * 16, acc[i][j], 32, wmma::mem_row_major);
    __syncwarp();

    const int nw0 = n0 + wn * 32;
    #pragma unroll
    for (int l = 0; l < 16; l++) {
        int idx = lane + l * 32;
        int r   = idx >> 3;
        int c4  = (idx & 7) * 4;
        float4 v = *(const float4*)(stg + r * 32 + c4);
        float4 bv = *(const float4*)&bias[nw0 + c4];
        v.x += bv.x; v.y += bv.y; v.z += bv.z; v.w += bv.w;
        const int m = m0 + wm * 64 + r;
        if (MODE == 0) {
            const int b = m >> 11, sq = m & 2047;
            const int hd = nw0 >> 6, d0 = (nw0 & 63) + c4;
            const size_t o = ((((size_t)b * HH + hd) * SS) + sq) * DD + d0;
            const float sc = (z == 0) ? 0.125f : 1.0f;
            __half* dst = (z == 0) ? g_qh : (z == 1) ? g_kh : g_vh;
            *(__half2*)(dst + o)     = __floats2half2_rn(v.x * sc, v.y * sc);
            *(__half2*)(dst + o + 2) = __floats2half2_rn(v.z * sc, v.w * sc);
        } else {
            *(float4*)&outp[(size_t)m * 1024 + nw0 + c4] = v;
        }
    }
}

// ---------------- WMMA fp16 flash attention, in-register softmax ----------------
#define KT_LD 72
#define KT_E  (64 * KT_LD)
#define F_LD  68
#define ATTN_SMEM (6 * KT_E * 2 + 64 * F_LD * 4)   // 72704

__global__ __launch_bounds__(128)
void attn3()
{
    extern __shared__ char smraw[];
    __half* sQ = (__half*)smraw;
    __half* sK = sQ + KT_E;              // [2][KT_E]
    __half* sV = sK + 2 * KT_E;          // [2][KT_E]
    __half* sP = sV + 2 * KT_E;
    float* sS = (float*)(sP + KT_E);     // discovery + epilogue staging only

    const int tid  = threadIdx.x;
    const int warp = tid >> 5;
    const int qt = blockIdx.x, hh = blockIdx.y, bb = blockIdx.z;
    const int row  = tid >> 1;
    const int half = tid & 1;
    const size_t hbase = (((size_t)bb * HH + hh) * SS) * DD;

    // Q group
    {
        const __half* qtile = g_qh + hbase + (size_t)qt * 64 * DD;
        #pragma unroll
        for (int i = 0; i < 4; i++) {
            int u = i * 128 + tid;
            int r = u >> 3, sg = u & 7;
            CP_ASYNC16(smem_u32(sQ + r * KT_LD + sg * 8), qtile + r * 64 + sg * 8);
        }
        CP_ASYNC_COMMIT();
    }
    // kt=0 K/V into buffer 0
    {
        const __half* kt0 = g_kh + hbase;
        const __half* vt0 = g_vh + hbase;
        #pragma unroll
        for (int i = 0; i < 4; i++) {
            int u = i * 128 + tid;
            int r = u >> 3, sg = u & 7;
            int so = r * KT_LD + sg * 8, go = r * 64 + sg * 8;
            CP_ASYNC16(smem_u32(sK + so), kt0 + go);
            CP_ASYNC16(smem_u32(sV + so), vt0 + go);
        }
        CP_ASYNC_COMMIT();
    }

    // layout discovery: acc element -> (row, col) via value = row*16 + col
    for (int i = tid; i < 256; i += 128)
        sS[(i >> 4) * F_LD + (i & 15)] = (float)i;
    __syncthreads();
    int rowidx[8], colidx[8];
    {
        wmma::fragment<wmma::accumulator, 16, 16, 16, float> rfrag;
        wmma::load_matrix_sync(rfrag, sS, F_LD, wmma::mem_row_major);
        #pragma unroll
        for (int i = 0; i < 8; i++) {
            int v = (int)rfrag.x[i];
            rowidx[i] = v >> 4;
            colidx[i] = v & 15;
        }
    }
    int rlo = rowidx[0];
    #pragma unroll
    for (int i = 1; i < 8; i++) rlo = min(rlo, rowidx[i]);
    bool isLo[8];
    #pragma unroll
    for (int i = 0; i < 8; i++) isLo[i] = (rowidx[i] == rlo);
    bool paired = true;
    #pragma unroll
    for (int p4 = 0; p4 < 4; p4++)
        paired = paired && (rowidx[2*p4+1] == rowidx[2*p4]) && (colidx[2*p4+1] == colidx[2*p4] + 1);

    CP_ASYNC_WAIT1();   // Q done
    __syncthreads();    // discovery loads done; Q visible

    wmma::fragment<wmma::matrix_a, 16, 16, 16, __half, wmma::row_major> aQ[4];
    #pragma unroll
    for (int kk = 0; kk < 4; kk++)
        wmma::load_matrix_sync(aQ[kk], sQ + (size_t)(warp * 16) * KT_LD + kk * 16, KT_LD);

    wmma::fragment<wmma::accumulator, 16, 16, 16, float> accO[4];
    #pragma unroll
    for (int j = 0; j < 4; j++) wmma::fill_fragment(accO[j], 0.0f);

    float m_lo = -INFINITY, m_hi = -INFINITY;
    float l_lo = 0.0f, l_hi = 0.0f;

    for (int kt = 0; kt <= qt; kt++) {
        __syncthreads();
        if (kt < qt) {
            const __half* kn = g_kh + hbase + (size_t)(kt + 1) * 64 * DD;
            const __half* vn = g_vh + hbase + (size_t)(kt + 1) * 64 * DD;
            __half* dK = sK + ((kt + 1) & 1) * KT_E;
            __half* dV = sV + ((kt + 1) & 1) * KT_E;
            #pragma unroll
            for (int i = 0; i < 4; i++) {
                int u = i * 128 + tid;
                int r = u >> 3, sg = u & 7;
                int so = r * KT_LD + sg * 8, go = r * 64 + sg * 8;
                CP_ASYNC16(smem_u32(dK + so), kn + go);
                CP_ASYNC16(smem_u32(dV + so), vn + go);
            }
            CP_ASYNC_COMMIT();
            CP_ASYNC_WAIT1();
        } else {
            CP_ASYNC_WAIT0();
        }
        __syncthreads();

        const __half* cK = sK + (kt & 1) * KT_E;
        const __half* cV = sV + (kt & 1) * KT_E;

        // ---- scores into registers ----
        wmma::fragment<wmma::accumulator, 16, 16, 16, float> accS[4];
        #pragma unroll
        for (int j = 0; j < 4; j++) wmma::fill_fragment(accS[j], 0.0f);
        #pragma unroll
        for (int kk = 0; kk < 4; kk++) {
            #pragma unroll
            for (int j = 0; j < 4; j++) {
                wmma::fragment<wmma::matrix_b, 16, 16, 16, __half, wmma::col_major> bK;
                wmma::load_matrix_sync(bK, cK + (size_t)(j * 16) * KT_LD + kk * 16, KT_LD);
                wmma::mma_sync(accS[j], aQ[kk], bK, accS[j]);
            }
        }

        // ---- in-register softmax ----
        const bool diag = (kt == qt);
        if (diag) {
            #pragma unroll
            for (int j = 0; j < 4; j++)
                #pragma unroll
                for (int i = 0; i < 8; i++)
                    if (j * 16 + colidx[i] > warp * 16 + rowidx[i]) accS[j].x[i] = -INFINITY;
        }
        float mx_lo = -INFINITY, mx_hi = -INFINITY;
        #pragma unroll
        for (int j = 0; j < 4; j++)
            #pragma unroll
            for (int i = 0; i < 8; i++) {
                float v = accS[j].x[i];
                if (isLo[i]) mx_lo = fmaxf(mx_lo, v); else mx_hi = fmaxf(mx_hi, v);
            }
        mx_lo = fmaxf(mx_lo, __shfl_xor_sync(0xffffffffu, mx_lo, 1));
        mx_lo = fmaxf(mx_lo, __shfl_xor_sync(0xffffffffu, mx_lo, 2));
        mx_hi = fmaxf(mx_hi, __shfl_xor_sync(0xffffffffu, mx_hi, 1));
        mx_hi = fmaxf(mx_hi, __shfl_xor_sync(0xffffffffu, mx_hi, 2));
        const float mn_lo = fmaxf(m_lo, mx_lo);
        const float mn_hi = fmaxf(m_hi, mx_hi);
        const float al_lo = __expf(m_lo - mn_lo);
        const float al_hi = __expf(m_hi - mn_hi);
        float ps_lo = 0.0f, ps_hi = 0.0f;
        #pragma unroll
        for (int j = 0; j < 4; j++)
            #pragma unroll
            for (int i = 0; i < 8; i++) {
                float p = __expf(accS[j].x[i] - (isLo[i] ? mn_lo : mn_hi));
                accS[j].x[i] = p;
                if (isLo[i]) ps_lo += p; else ps_hi += p;
            }
        ps_lo += __shfl_xor_sync(0xffffffffu, ps_lo, 1);
        ps_lo += __shfl_xor_sync(0xffffffffu, ps_lo, 2);
        ps_hi += __shfl_xor_sync(0xffffffffu, ps_hi, 1);
        ps_hi += __shfl_xor_sync(0xffffffffu, ps_hi, 2);
        l_lo = l_lo * al_lo + ps_lo;  m_lo = mn_lo;
        l_hi = l_hi * al_hi + ps_hi;  m_hi = mn_hi;

        // ---- store P (warp-private rows) ----
        if (paired) {
            #pragma unroll
            for (int j = 0; j < 4; j++)
                #pragma unroll
                for (int p4 = 0; p4 < 4; p4++) {
                    const int i0 = 2 * p4;
                    __half2 hv = __floats2half2_rn(accS[j].x[i0], accS[j].x[i0 + 1]);
                    *(__half2*)(sP + (size_t)(warp * 16 + rowidx[i0]) * KT_LD + j * 16 + colidx[i0]) = hv;
                }
        } else {
            #pragma unroll
            for (int j = 0; j < 4; j++)
                #pragma unroll
                for (int i = 0; i < 8; i++)
                    sP[(size_t)(warp * 16 + rowidx[i]) * KT_LD + j * 16 + colidx[i]] = __float2half_rn(accS[j].x[i]);
        }
        __syncwarp();

        // ---- PV with in-register rescale ----
        #pragma unroll
        for (int j = 0; j < 4; j++)
            #pragma unroll
            for (int i = 0; i < 8; i++)
                accO[j].x[i] *= (isLo[i]) ? al_lo : al_hi;
        #pragma unroll
        for (int kk = 0; kk < 4; kk++) {
            wmma::fragment<wmma::matrix_a, 16, 16, 16, __half, wmma::row_major> aP;
            wmma::load_matrix_sync(aP, sP + (size_t)(warp * 16) * KT_LD + kk * 16, KT_LD);
            #pragma unroll
            for (int j = 0; j < 4; j++) {
                wmma::fragment<wmma::matrix_b, 16, 16, 16, __half, wmma::row_major> bV;
                wmma::load_matrix_sync(bV, cV + (size_t)(kk * 16) * KT_LD + j * 16, KT_LD);
                wmma::mma_sync(accO[j], aP, bV, accO[j]);
            }
        }
    }

    // epilogue: normalize in-register, stage via sS (warp-private), write fp16
    {
        const float inv_lo = 1.0f / l_lo;
        const float inv_hi = 1.0f / l_hi;
        #pragma unroll
        for (int j = 0; j < 4; j++)
            #pragma unroll
            for (int i = 0; i < 8; i++)
                accO[j].x[i] *= (isLo[i]) ? inv_lo : inv_hi;
        #pragma unroll
        for (int j = 0; j < 4; j++)
            wmma::store_matrix_sync(sS + (size_t)(warp * 16) * F_LD + j * 16, accO[j], F_LD, wmma::mem_row_major);
    }
    __syncwarp();
    {
        const float* orow = sS + (size_t)row * F_LD + half * 32;
        const size_t go = ((size_t)bb * SS + (size_t)qt * 64 + row) * EE + hh * DD + half * 32;
        #pragma unroll
        for (int c8 = 0; c8 < 8; c8++) {
            float4 v = *(const float4*)(orow + 4 * c8);
            *(__half2*)(g_xh + go + 4*c8)     = __floats2half2_rn(v.x, v.y);
            *(__half2*)(g_xh + go + 4*c8 + 2) = __floats2half2_rn(v.z, v.w);
        }
    }
}

// ---------------------------------------------------------------------------
extern "C" void kernel_launch(void* const* d_in, const int* in_sizes, int n_in,
                              void* d_out, int out_size)
{
    const float* x  = (const float*)d_in[0];
    const float* Wq = (const float*)d_in[1];
    const float* bq = (const float*)d_in[2];
    const float* Wk = (const float*)d_in[3];
    const float* bk = (const float*)d_in[4];
    const float* Wv = (const float*)d_in[5];
    const float* bv = (const float*)d_in[6];
    const float* Wo = (const float*)d_in[7];
    const float* bo = (const float*)d_in[8];
    float* out = (float*)d_out;

    cudaFuncSetAttribute(wgemm<0>, cudaFuncAttributeMaxDynamicSharedMemorySize, GEMM_SMEM);
    cudaFuncSetAttribute(wgemm<1>, cudaFuncAttributeMaxDynamicSharedMemorySize, GEMM_SMEM);
    cudaFuncSetAttribute(attn3,    cudaFuncAttributeMaxDynamicSharedMemorySize, ATTN_SMEM);

    conv_x<<<MM * EE / 2048, 256>>>(x);
    conv_w4<<<dim3(32, 32, 4), 256>>>(Wq, Wk, Wv, Wo);
    wgemm<0><<<dim3(EE / 128, MM / 128, 3), 256, GEMM_SMEM>>>(bq, bk, bv, nullptr);
    attn3<<<dim3(SS / 64, HH, BB), 128, ATTN_SMEM>>>();
    wgemm<1><<<dim3(EE / 128, MM / 128, 1), 256, GEMM_SMEM>>>(bo, nullptr, nullptr, out);
}